// round 11
// baseline (speedup 1.0000x reference)
#include <cuda_runtime.h>
#include <cuda_fp16.h>
#include <cstdint>

#define B_SZ 2
#define S_LEN 2048
#define HID_C 2048
#define N_HEADS 16
#define HEAD_D 128
#define M_ROWS (B_SZ * S_LEN)   /* 4096 */
#define KV_C 256

#define SOFTMAX_SCALE_LOG2 0.12754404735576283f       /* 1/sqrt(128)*log2(e) */

// ---------------------------------------------------------------------------
// Device-global scratch (allocation-free rule)
// ---------------------------------------------------------------------------
__device__ __half gA_hi[(size_t)M_ROWS * HID_C];   // hs / attn hi (left operand)
__device__ __half gA_lo[(size_t)M_ROWS * HID_C];
__device__ __half gQhi[(size_t)M_ROWS * HID_C];    // pre-scaled by 1/sqrt(d)*log2e
__device__ __half gQlo[(size_t)M_ROWS * HID_C];
__device__ __half gKhi[(size_t)M_ROWS * HEAD_D];          // right operand: hi only
__device__ __half gVthi[(size_t)HEAD_D * M_ROWS];         // V^T [d][bS], hi only
__device__ __half gWq_hi[(size_t)HID_C * HID_C];
__device__ __half gWkv_hi[(size_t)KV_C * HID_C];
__device__ __half gWp_hi[(size_t)HID_C * HID_C];

__device__ __forceinline__ uint32_t smem_to_u32(const void* p) {
    uint32_t a;
    asm("{ .reg .u64 t; cvta.to.shared.u64 t, %1; cvt.u32.u64 %0, t; }"
        : "=r"(a) : "l"(p));
    return a;
}

#define CP_ASYNC16(sm, g) \
    asm volatile("cp.async.cg.shared.global [%0], [%1], 16;" \
                 :: "r"(sm), "l"(g) : "memory")
#define CP_COMMIT() asm volatile("cp.async.commit_group;" ::: "memory")
#define CP_WAIT1()  asm volatile("cp.async.wait_group 1;" ::: "memory")
#define CP_WAIT0()  asm volatile("cp.async.wait_group 0;" ::: "memory")

#define LDMATRIX_X4(r0, r1, r2, r3, addr) \
    asm volatile("ldmatrix.sync.aligned.m8n8.x4.shared.b16 {%0,%1,%2,%3}, [%4];" \
                 : "=r"(r0), "=r"(r1), "=r"(r2), "=r"(r3) : "r"(addr))

#define MMA_F16(d, a, b) \
    asm volatile("mma.sync.aligned.m16n8k16.row.col.f32.f16.f16.f32 " \
                 "{%0,%1,%2,%3}, {%4,%5,%6,%7}, {%8,%9}, {%0,%1,%2,%3};" \
                 : "+f"((d)[0]), "+f"((d)[1]), "+f"((d)[2]), "+f"((d)[3]) \
                 : "r"((a)[0]), "r"((a)[1]), "r"((a)[2]), "r"((a)[3]), \
                   "r"((b)[0]), "r"((b)[1]))

__device__ __forceinline__ uint32_t pack_h2(__half x, __half y) {
    __half2 t; t.x = x; t.y = y;
    return *reinterpret_cast<uint32_t*>(&t);
}
// fp32 pair -> fp16 hi + fp16 lo(residual)
__device__ __forceinline__ void split2h(float v0, float v1,
                                        uint32_t& hi, uint32_t& lo) {
    __half h0 = __float2half_rn(v0);
    __half h1 = __float2half_rn(v1);
    hi = pack_h2(h0, h1);
    lo = pack_h2(__float2half_rn(v0 - __half2float(h0)),
                 __float2half_rn(v1 - __half2float(h1)));
}
__device__ __forceinline__ uint32_t pack2h(float v0, float v1) {
    __half2 t = __floats2half2_rn(v0, v1);
    return *reinterpret_cast<uint32_t*>(&t);
}

// ---------------------------------------------------------------------------
// fp32 -> (hi, lo) fp16 split, elementwise
// ---------------------------------------------------------------------------
__global__ void split_f32_kernel(const float* __restrict__ src,
                                 __half* __restrict__ hi,
                                 __half* __restrict__ lo, int n4)
{
    int i = blockIdx.x * blockDim.x + threadIdx.x;
    if (i >= n4) return;
    float4 v = ((const float4*)src)[i];
    uint32_t h0, l0, h1, l1;
    split2h(v.x, v.y, h0, l0);
    split2h(v.z, v.w, h1, l1);
    ((uint32_t*)hi)[2 * i] = h0;
    ((uint32_t*)hi)[2 * i + 1] = h1;
    ((uint32_t*)lo)[2 * i] = l0;
    ((uint32_t*)lo)[2 * i + 1] = l1;
}

// ---------------------------------------------------------------------------
// Fused weight transpose+convert: z=0 Wq, z=1 Wp, z=2 Wkv
// ---------------------------------------------------------------------------
__global__ void tconv_all_kernel(const float* __restrict__ Wq,
                                 const float* __restrict__ Wp,
                                 const float* __restrict__ Wkv)
{
    const int z = blockIdx.z;
    const float* W = (z == 0) ? Wq : (z == 1) ? Wp : Wkv;
    __half* T = (z == 0) ? gWq_hi : (z == 1) ? gWp_hi : gWkv_hi;
    const int N = (z == 2) ? KV_C : HID_C;
    if (blockIdx.x * 32 >= N) return;

    __shared__ float tile[32][33];
    int n0 = blockIdx.x * 32, k0 = blockIdx.y * 32;
    int tx = threadIdx.x, ty = threadIdx.y;
#pragma unroll
    for (int j = 0; j < 32; j += 8)
        tile[ty + j][tx] = W[(size_t)(k0 + ty + j) * N + n0 + tx];
    __syncthreads();
#pragma unroll
    for (int j = 0; j < 32; j += 8)
        T[(size_t)(n0 + ty + j) * HID_C + k0 + tx] =
            __float2half_rn(tile[tx][ty + j]);
}

// ---------------------------------------------------------------------------
// mma.sync fp16 GEMM: C = (Ah+Al) @ Bh^T + bias   (2-product emulation)
// CTA 128x128, 128 threads (4 warps 2x2), warp tile 64x64 -> 128B/MMA smem
// traffic (crossbar-balanced). K-chunk 64 halves, 3-stage cp.async, 2 CTA/SM.
// mode 0: out-proj -> fp32 C (B0 = Wp)
// mode 1: fused QKV: bx<16 -> Q (B0=Wq) scaled+split -> gQhi/gQlo
//                    bx>=16 -> KV (B1=Wkv): bn==0 -> K hi; bn==128 -> V^T hi
// ---------------------------------------------------------------------------
#define BM 128
#define BN 128
#define BKH 64                  /* halves per chunk */
#define APITCH_B 144            /* 128B data + 16B pad */
#define STG_A (BM * APITCH_B)   /* 18432 */
#define STG_B (BN * APITCH_B)
#define STG_BYTES (STG_A + STG_B)  /* 36864 */
#define NSTAGE 3
#define GEMM_SMEM (NSTAGE * STG_BYTES)  /* 110592 */
#define NCHUNK 64               /* 2 phases * 32 chunks */

__global__ __launch_bounds__(128, 2)
void mma_gemm_kernel(const __half* __restrict__ Ahi,
                     const __half* __restrict__ Alo,
                     const __half* __restrict__ B0,
                     const float* __restrict__ bias0,
                     const __half* __restrict__ B1,
                     const float* __restrict__ bias1,
                     float* __restrict__ C, int N, int mode)
{
    extern __shared__ char smem[];
    const uint32_t smem_base = smem_to_u32(smem);
    const int tid = threadIdx.x;
    const int wid = tid >> 5;
    const int lid = tid & 31;
    const int bm = blockIdx.y * BM;
    const bool isKV = (mode == 1) && (blockIdx.x >= 16);
    const int bn = isKV ? (blockIdx.x - 16) * BN : blockIdx.x * BN;
    const __half* Bh = isKV ? B1 : B0;
    const float* bias = isKV ? bias1 : bias0;

    auto issue = [&](int c, int stage) {
        const __half* Asrc = (c >> 5) ? Alo : Ahi;
        const size_t k0 = (size_t)(c & 31) * BKH;
        const uint32_t sA = smem_base + stage * STG_BYTES;
        const uint32_t sB = sA + STG_A;
#pragma unroll
        for (int j = 0; j < 8; j++) {
            int seg = tid + j * 128;
            int r = seg >> 3, s = seg & 7;
            CP_ASYNC16(sA + r * APITCH_B + s * 16,
                       (const char*)(Asrc + (size_t)(bm + r) * HID_C + k0 + s * 8));
        }
#pragma unroll
        for (int j = 0; j < 8; j++) {
            int seg = tid + j * 128;
            int r = seg >> 3, s = seg & 7;
            CP_ASYNC16(sB + r * APITCH_B + s * 16,
                       (const char*)(Bh + (size_t)(bn + r) * HID_C + k0 + s * 8));
        }
    };

    float acc[4][8][4];
#pragma unroll
    for (int i = 0; i < 4; i++)
#pragma unroll
        for (int j = 0; j < 8; j++)
#pragma unroll
            for (int q = 0; q < 4; q++) acc[i][j][q] = 0.f;

    issue(0, 0); CP_COMMIT();
    issue(1, 1); CP_COMMIT();

    const int wm = (wid >> 1) * 64;
    const int wn = (wid & 1) * 64;
    const int mat = lid >> 3;
    const int wi = lid & 7;

    for (int t = 0; t < NCHUNK; t++) {
        CP_WAIT1();
        __syncthreads();
        if (t + 2 < NCHUNK) issue(t + 2, (t + 2) % NSTAGE);
        CP_COMMIT();

        const uint32_t aBase = smem_base + (t % NSTAGE) * STG_BYTES;
        const uint32_t bBase = aBase + STG_A;
#pragma unroll
        for (int ks = 0; ks < 4; ks++) {
            const int k0 = ks * 16;
            uint32_t afr[4][4];
            uint32_t bfr[8][2];
#pragma unroll
            for (int i = 0; i < 4; i++) {
                int row = wm + i * 16 + (mat & 1) * 8 + wi;
                int col = k0 + (mat >> 1) * 8;
                LDMATRIX_X4(afr[i][0], afr[i][1], afr[i][2], afr[i][3],
                            aBase + row * APITCH_B + col * 2);
            }
#pragma unroll
            for (int jj = 0; jj < 4; jj++) {
                int n = wn + jj * 16 + (mat >> 1) * 8 + wi;
                int k = k0 + (mat & 1) * 8;
                LDMATRIX_X4(bfr[2 * jj][0], bfr[2 * jj][1],
                            bfr[2 * jj + 1][0], bfr[2 * jj + 1][1],
                            bBase + n * APITCH_B + k * 2);
            }
#pragma unroll
            for (int i = 0; i < 4; i++)
#pragma unroll
                for (int j = 0; j < 8; j++)
                    MMA_F16(acc[i][j], afr[i], bfr[j]);
        }
    }

    const int g = lid >> 2;
    const int tq = lid & 3;
#pragma unroll
    for (int i = 0; i < 4; i++) {
#pragma unroll
        for (int j = 0; j < 8; j++) {
            int row0 = bm + wm + i * 16 + g;
            int col = bn + wn + j * 8 + tq * 2;
            float b0 = bias[col], b1 = bias[col + 1];
            float v00 = acc[i][j][0] + b0, v01 = acc[i][j][1] + b1;
            float v10 = acc[i][j][2] + b0, v11 = acc[i][j][3] + b1;
            if (mode == 0) {
                *(float2*)(C + (size_t)row0 * N + col) = make_float2(v00, v01);
                *(float2*)(C + (size_t)(row0 + 8) * N + col) = make_float2(v10, v11);
            } else if (!isKV) {   // Q: fold softmax scale (log2 domain), split
                v00 *= SOFTMAX_SCALE_LOG2; v01 *= SOFTMAX_SCALE_LOG2;
                v10 *= SOFTMAX_SCALE_LOG2; v11 *= SOFTMAX_SCALE_LOG2;
                uint32_t h, l;
                split2h(v00, v01, h, l);
                *(uint32_t*)&gQhi[(size_t)row0 * HID_C + col] = h;
                *(uint32_t*)&gQlo[(size_t)row0 * HID_C + col] = l;
                split2h(v10, v11, h, l);
                *(uint32_t*)&gQhi[(size_t)(row0 + 8) * HID_C + col] = h;
                *(uint32_t*)&gQlo[(size_t)(row0 + 8) * HID_C + col] = l;
            } else {
                if (bn == 0) {    // K: hi only
                    *(uint32_t*)&gKhi[(size_t)row0 * HEAD_D + col] =
                        pack2h(v00, v01);
                    *(uint32_t*)&gKhi[(size_t)(row0 + 8) * HEAD_D + col] =
                        pack2h(v10, v11);
                } else {          // V: transpose, hi only
                    int d0 = col - 128;
                    float vs[2][2] = {{v00, v01}, {v10, v11}};
#pragma unroll
                    for (int rr = 0; rr < 2; rr++)
#pragma unroll
                        for (int cc = 0; cc < 2; cc++)
                            gVthi[(size_t)(d0 + cc) * M_ROWS + row0 + rr * 8] =
                                __float2half_rn(vs[rr][cc]);
                }
            }
        }
    }
}

// ---------------------------------------------------------------------------
// Flash attention, tensor-core fp16; Q carries hi+lo, K/V/P hi only; causal.
// CTA: 128 q-rows x (head, batch); 8 warps (m16); KV tile FN=128.
// QK^T loads each K fragment once; PV is single-pass (P rounded to fp16).
// ---------------------------------------------------------------------------
#define FM 128
#define FN 128
#define SMQ_HI 0
#define SMQ_LO 32768
#define SM_STG 65536
#define STGSZ 65536
#define SK_OFF 0
#define SV_OFF 32768
#define FA_SMEM (65536 + 2 * STGSZ)   /* 196608 */

__global__ __launch_bounds__(256, 1)
void flash_mma_kernel()
{
    extern __shared__ char sm[];
    const uint32_t sb = smem_to_u32(sm);
    const int tid = threadIdx.x;
    const int wid = tid >> 5;
    const int lid = tid & 31;
    const int qt = (int)gridDim.x - 1 - (int)blockIdx.x;  // heavy blocks first
    const int h = blockIdx.y;
    const int b = blockIdx.z;
    const int m0 = qt * FM;
    const int wm = wid * 16;
    const size_t bS = (size_t)b * S_LEN;
    const int g = lid >> 2, tq = lid & 3;
    const int ntiles = qt + 1;

    auto issueQ = [&]() {
#pragma unroll
        for (int j = 0; j < 16; j++) {
            int idx = tid + j * 256;
            int arr = idx >> 11;
            int rem = idx & 2047;
            int r = rem >> 4, c16 = rem & 15;
            const __half* src =
                (arr ? gQlo : gQhi) + (bS + m0 + r) * HID_C + h * HEAD_D + c16 * 8;
            CP_ASYNC16(sb + (arr ? SMQ_LO : SMQ_HI) + r * 256 + ((c16 ^ (r & 7)) << 4),
                       (const char*)src);
        }
    };
    auto issueKV = [&](int t, int s) {
        const uint32_t st = sb + SM_STG + s * STGSZ;
        const int n0 = t * FN;
#pragma unroll
        for (int j = 0; j < 8; j++) {
            int idx = tid + j * 256;
            int r = idx >> 4, c16 = idx & 15;
            const __half* src = gKhi + (bS + n0 + r) * HEAD_D + c16 * 8;
            CP_ASYNC16(st + SK_OFF + r * 256 + ((c16 ^ (r & 7)) << 4),
                       (const char*)src);
        }
#pragma unroll
        for (int j = 0; j < 8; j++) {
            int idx = tid + j * 256;
            int r = idx >> 4, c16 = idx & 15;
            const __half* src = gVthi + (size_t)r * M_ROWS + bS + n0 + c16 * 8;
            CP_ASYNC16(st + SV_OFF + r * 256 + ((c16 ^ (r & 7)) << 4),
                       (const char*)src);
        }
    };

    issueQ();
    issueKV(0, 0);
    CP_COMMIT();
    if (ntiles > 1) issueKV(1, 1);
    CP_COMMIT();
    CP_WAIT1();
    __syncthreads();

    float oacc[16][4];
#pragma unroll
    for (int i = 0; i < 16; i++)
#pragma unroll
        for (int q = 0; q < 4; q++) oacc[i][q] = 0.f;
    float mst[2] = {-1e30f, -1e30f};
    float lst[2] = {0.f, 0.f};

    const int mat = lid >> 3;
    const int wi = lid & 7;

    for (int t = 0; t < ntiles; t++) {
        const uint32_t st = sb + SM_STG + (t & 1) * STGSZ;

        // ---- S = (Qh + Ql) K^T : K fragments loaded once ----
        float sacc[16][4];
#pragma unroll
        for (int i = 0; i < 16; i++)
#pragma unroll
            for (int q = 0; q < 4; q++) sacc[i][q] = 0.f;

        {
            const uint32_t kb = st + SK_OFF;
#pragma unroll
            for (int kk = 0; kk < 8; kk++) {
                uint32_t ah[4], alq[4];
                {
                    int r = wm + (lid & 15);
                    int c16 = 2 * kk + (lid >> 4);
                    uint32_t off = r * 256 + ((c16 ^ (r & 7)) << 4);
                    LDMATRIX_X4(ah[0], ah[1], ah[2], ah[3], sb + SMQ_HI + off);
                    LDMATRIX_X4(alq[0], alq[1], alq[2], alq[3], sb + SMQ_LO + off);
                }
#pragma unroll
                for (int jj = 0; jj < 8; jj++) {
                    int r = jj * 16 + (mat >> 1) * 8 + wi;
                    int c16 = 2 * kk + (mat & 1);
                    uint32_t v[4];
                    LDMATRIX_X4(v[0], v[1], v[2], v[3],
                                kb + r * 256 + ((c16 ^ (r & 7)) << 4));
                    MMA_F16(sacc[2 * jj], ah, v);
                    MMA_F16(sacc[2 * jj + 1], ah, (v + 2));
                    MMA_F16(sacc[2 * jj], alq, v);
                    MMA_F16(sacc[2 * jj + 1], alq, (v + 2));
                }
            }
        }

        // ---- causal mask (diagonal tile only) ----
        if (t == qt) {
#pragma unroll
            for (int nb = 0; nb < 16; nb++)
#pragma unroll
                for (int q = 0; q < 4; q++) {
                    int col = t * FN + nb * 8 + tq * 2 + (q & 1);
                    int row = m0 + wm + g + (q >> 1) * 8;
                    if (col > row) sacc[nb][q] = -1e30f;
                }
        }

        // ---- online softmax (log2 domain) ----
#pragma unroll
        for (int hf = 0; hf < 2; hf++) {
            float tm = -1e30f;
#pragma unroll
            for (int nb = 0; nb < 16; nb++) {
                tm = fmaxf(tm, fmaxf(sacc[nb][2 * hf], sacc[nb][2 * hf + 1]));
            }
            tm = fmaxf(tm, __shfl_xor_sync(0xffffffffu, tm, 1));
            tm = fmaxf(tm, __shfl_xor_sync(0xffffffffu, tm, 2));
            float mn = fmaxf(mst[hf], tm);
            float corr = exp2f(mst[hf] - mn);
            mst[hf] = mn;
            float sum = 0.f;
#pragma unroll
            for (int nb = 0; nb < 16; nb++) {
#pragma unroll
                for (int e = 0; e < 2; e++) {
                    float p = exp2f(sacc[nb][2 * hf + e] - mn);
                    sacc[nb][2 * hf + e] = p;
                    sum += p;
                }
            }
            sum += __shfl_xor_sync(0xffffffffu, sum, 1);
            sum += __shfl_xor_sync(0xffffffffu, sum, 2);
            lst[hf] = lst[hf] * corr + sum;
#pragma unroll
            for (int nb = 0; nb < 16; nb++) {
                oacc[nb][2 * hf + 0] *= corr;
                oacc[nb][2 * hf + 1] *= corr;
            }
        }

        // ---- O += Ph Vh (single-pass PV; P rounded to fp16) ----
#pragma unroll
        for (int kk = 0; kk < 8; kk++) {
            uint32_t ah[4];
            ah[0] = pack2h(sacc[2 * kk][0], sacc[2 * kk][1]);
            ah[1] = pack2h(sacc[2 * kk][2], sacc[2 * kk][3]);
            ah[2] = pack2h(sacc[2 * kk + 1][0], sacc[2 * kk + 1][1]);
            ah[3] = pack2h(sacc[2 * kk + 1][2], sacc[2 * kk + 1][3]);
#pragma unroll
            for (int jj = 0; jj < 8; jj++) {
                int r = jj * 16 + (mat >> 1) * 8 + wi;
                int c16 = 2 * kk + (mat & 1);
                uint32_t v[4];
                LDMATRIX_X4(v[0], v[1], v[2], v[3],
                            st + SV_OFF + r * 256 + ((c16 ^ (r & 7)) << 4));
                MMA_F16(oacc[2 * jj], ah, v);
                MMA_F16(oacc[2 * jj + 1], ah, (v + 2));
            }
        }

        __syncthreads();
        if (t + 2 < ntiles) issueKV(t + 2, t & 1);
        CP_COMMIT();
        if (t + 1 < ntiles) {
            CP_WAIT1();
        } else {
            CP_WAIT0();
        }
        __syncthreads();
    }

    // ---- epilogue: O/l -> fp16 hi/lo into gA ----
#pragma unroll
    for (int hf = 0; hf < 2; hf++) {
        float inv = 1.f / lst[hf];
        size_t row = bS + m0 + wm + g + hf * 8;
#pragma unroll
        for (int nb = 0; nb < 16; nb++) {
            float v0 = oacc[nb][2 * hf] * inv;
            float v1 = oacc[nb][2 * hf + 1] * inv;
            uint32_t hh, ll;
            split2h(v0, v1, hh, ll);
            size_t off = row * HID_C + h * HEAD_D + nb * 8 + tq * 2;
            *(uint32_t*)&gA_hi[off] = hh;
            *(uint32_t*)&gA_lo[off] = ll;
        }
    }
}

// ---------------------------------------------------------------------------
extern "C" void kernel_launch(void* const* d_in, const int* in_sizes, int n_in,
                              void* d_out, int out_size)
{
    (void)in_sizes; (void)n_in; (void)out_size;
    const float* hs  = (const float*)d_in[0];
    /* d_in[1] = attention_mask (exact causal tril) applied analytically */
    const float* Wq  = (const float*)d_in[2];
    const float* bq  = (const float*)d_in[3];
    const float* Wkv = (const float*)d_in[4];
    const float* bkv = (const float*)d_in[5];
    const float* Wp  = (const float*)d_in[6];
    const float* bp  = (const float*)d_in[7];
    float* out = (float*)d_out;

    __half *pAhi, *pAlo, *pWqh, *pWkh, *pWph;
    cudaGetSymbolAddress((void**)&pAhi, gA_hi);
    cudaGetSymbolAddress((void**)&pAlo, gA_lo);
    cudaGetSymbolAddress((void**)&pWqh, gWq_hi);
    cudaGetSymbolAddress((void**)&pWkh, gWkv_hi);
    cudaGetSymbolAddress((void**)&pWph, gWp_hi);

    cudaFuncSetAttribute(mma_gemm_kernel,
                         cudaFuncAttributeMaxDynamicSharedMemorySize, GEMM_SMEM);
    cudaFuncSetAttribute(flash_mma_kernel,
                         cudaFuncAttributeMaxDynamicSharedMemorySize, FA_SMEM);

    // 1. split hidden states into fp16 hi/lo
    {
        int n4 = M_ROWS * HID_C / 4;
        split_f32_kernel<<<(n4 + 255) / 256, 256>>>(hs, pAhi, pAlo, n4);
    }
    // 2. fused transpose+convert of all three weights
    tconv_all_kernel<<<dim3(HID_C / 32, HID_C / 32, 3), dim3(32, 8)>>>(Wq, Wp, Wkv);

    // 3. fused Q + KV projection (grid.x: 16 Q blocks + 2 KV blocks)
    mma_gemm_kernel<<<dim3(18, M_ROWS / BM), 128, GEMM_SMEM>>>(
        pAhi, pAlo, pWqh, bq, pWkh, bkv, nullptr, HID_C, 1);
    // 4. attention -> gA_hi/gA_lo
    flash_mma_kernel<<<dim3(S_LEN / FM, N_HEADS, B_SZ), 256, FA_SMEM>>>();
    // 5. out = attn @ Wp + bp
    mma_gemm_kernel<<<dim3(16, M_ROWS / BM), 128, GEMM_SMEM>>>(
        pAhi, pAlo, pWph, bp, nullptr, nullptr, out, HID_C, 0);
}

// round 12
// speedup vs baseline: 1.5251x; 1.5251x over previous
#include <cuda_runtime.h>
#include <cuda_fp16.h>
#include <cstdint>

#define B_SZ 2
#define S_LEN 2048
#define HID_C 2048
#define N_HEADS 16
#define HEAD_D 128
#define M_ROWS (B_SZ * S_LEN)   /* 4096 */
#define KV_C 256

#define SOFTMAX_SCALE_LOG2 0.12754404735576283f       /* 1/sqrt(128)*log2(e) */

// ---------------------------------------------------------------------------
// Device-global scratch (allocation-free rule)
// ---------------------------------------------------------------------------
__device__ __half gA_hi[(size_t)M_ROWS * HID_C];   // hs / attn hi (left operand)
__device__ __half gA_lo[(size_t)M_ROWS * HID_C];
__device__ __half gQhi[(size_t)M_ROWS * HID_C];    // pre-scaled by 1/sqrt(d)*log2e
__device__ __half gQlo[(size_t)M_ROWS * HID_C];
__device__ __half gKhi[(size_t)M_ROWS * HEAD_D];          // right operand: hi only
__device__ __half gVthi[(size_t)HEAD_D * M_ROWS];         // V^T [d][bS], hi only
__device__ __half gWq_hi[(size_t)HID_C * HID_C];
__device__ __half gWkv_hi[(size_t)KV_C * HID_C];
__device__ __half gWp_hi[(size_t)HID_C * HID_C];

__device__ __forceinline__ uint32_t smem_to_u32(const void* p) {
    uint32_t a;
    asm("{ .reg .u64 t; cvta.to.shared.u64 t, %1; cvt.u32.u64 %0, t; }"
        : "=r"(a) : "l"(p));
    return a;
}

#define CP_ASYNC16(sm, g) \
    asm volatile("cp.async.cg.shared.global [%0], [%1], 16;" \
                 :: "r"(sm), "l"(g) : "memory")
#define CP_COMMIT() asm volatile("cp.async.commit_group;" ::: "memory")
#define CP_WAIT1()  asm volatile("cp.async.wait_group 1;" ::: "memory")
#define CP_WAIT0()  asm volatile("cp.async.wait_group 0;" ::: "memory")

#define LDMATRIX_X4(r0, r1, r2, r3, addr) \
    asm volatile("ldmatrix.sync.aligned.m8n8.x4.shared.b16 {%0,%1,%2,%3}, [%4];" \
                 : "=r"(r0), "=r"(r1), "=r"(r2), "=r"(r3) : "r"(addr))

#define MMA_F16(d, a, b) \
    asm volatile("mma.sync.aligned.m16n8k16.row.col.f32.f16.f16.f32 " \
                 "{%0,%1,%2,%3}, {%4,%5,%6,%7}, {%8,%9}, {%0,%1,%2,%3};" \
                 : "+f"((d)[0]), "+f"((d)[1]), "+f"((d)[2]), "+f"((d)[3]) \
                 : "r"((a)[0]), "r"((a)[1]), "r"((a)[2]), "r"((a)[3]), \
                   "r"((b)[0]), "r"((b)[1]))

__device__ __forceinline__ uint32_t pack_h2(__half x, __half y) {
    __half2 t; t.x = x; t.y = y;
    return *reinterpret_cast<uint32_t*>(&t);
}
// fp32 pair -> fp16 hi + fp16 lo(residual)
__device__ __forceinline__ void split2h(float v0, float v1,
                                        uint32_t& hi, uint32_t& lo) {
    __half h0 = __float2half_rn(v0);
    __half h1 = __float2half_rn(v1);
    hi = pack_h2(h0, h1);
    lo = pack_h2(__float2half_rn(v0 - __half2float(h0)),
                 __float2half_rn(v1 - __half2float(h1)));
}
__device__ __forceinline__ uint32_t pack2h(float v0, float v1) {
    __half2 t = __floats2half2_rn(v0, v1);
    return *reinterpret_cast<uint32_t*>(&t);
}

// ---------------------------------------------------------------------------
// fp32 -> (hi, lo) fp16 split, elementwise
// ---------------------------------------------------------------------------
__global__ void split_f32_kernel(const float* __restrict__ src,
                                 __half* __restrict__ hi,
                                 __half* __restrict__ lo, int n4)
{
    int i = blockIdx.x * blockDim.x + threadIdx.x;
    if (i >= n4) return;
    float4 v = ((const float4*)src)[i];
    uint32_t h0, l0, h1, l1;
    split2h(v.x, v.y, h0, l0);
    split2h(v.z, v.w, h1, l1);
    ((uint32_t*)hi)[2 * i] = h0;
    ((uint32_t*)hi)[2 * i + 1] = h1;
    ((uint32_t*)lo)[2 * i] = l0;
    ((uint32_t*)lo)[2 * i + 1] = l1;
}

// ---------------------------------------------------------------------------
// Fused weight transpose+convert: z=0 Wq, z=1 Wp, z=2 Wkv
// ---------------------------------------------------------------------------
__global__ void tconv_all_kernel(const float* __restrict__ Wq,
                                 const float* __restrict__ Wp,
                                 const float* __restrict__ Wkv)
{
    const int z = blockIdx.z;
    const float* W = (z == 0) ? Wq : (z == 1) ? Wp : Wkv;
    __half* T = (z == 0) ? gWq_hi : (z == 1) ? gWp_hi : gWkv_hi;
    const int N = (z == 2) ? KV_C : HID_C;
    if (blockIdx.x * 32 >= N) return;

    __shared__ float tile[32][33];
    int n0 = blockIdx.x * 32, k0 = blockIdx.y * 32;
    int tx = threadIdx.x, ty = threadIdx.y;
#pragma unroll
    for (int j = 0; j < 32; j += 8)
        tile[ty + j][tx] = W[(size_t)(k0 + ty + j) * N + n0 + tx];
    __syncthreads();
#pragma unroll
    for (int j = 0; j < 32; j += 8)
        T[(size_t)(n0 + ty + j) * HID_C + k0 + tx] =
            __float2half_rn(tile[tx][ty + j]);
}

// ---------------------------------------------------------------------------
// mma.sync fp16 GEMM: C = (Ah+Al) @ Bh^T + bias   (2-product emulation)
// K-chunk = 64 halves (128B/row, pitch 144 -> conflict-free ldmatrix)
// 256 threads, 8 warps (2x4), warp tile 64x32, 3-stage cp.async, 2 CTA/SM.
// mode 0: out-proj -> fp32 C (B0 = Wp)
// mode 1: fused QKV: bx<16 -> Q (B0=Wq) scaled+split -> gQhi/gQlo
//                    bx>=16 -> KV (B1=Wkv): bn==0 -> K hi; bn==128 -> V^T hi
// ---------------------------------------------------------------------------
#define BM 128
#define BN 128
#define BKH 64                  /* halves per chunk */
#define APITCH_B 144            /* 128B data + 16B pad */
#define STG_A (BM * APITCH_B)   /* 18432 */
#define STG_B (BN * APITCH_B)
#define STG_BYTES (STG_A + STG_B)  /* 36864 */
#define NSTAGE 3
#define GEMM_SMEM (NSTAGE * STG_BYTES)  /* 110592 */
#define NCHUNK 64               /* 2 phases * 32 chunks */

__global__ __launch_bounds__(256, 2)
void mma_gemm_kernel(const __half* __restrict__ Ahi,
                     const __half* __restrict__ Alo,
                     const __half* __restrict__ B0,
                     const float* __restrict__ bias0,
                     const __half* __restrict__ B1,
                     const float* __restrict__ bias1,
                     float* __restrict__ C, int N, int mode)
{
    extern __shared__ char smem[];
    const uint32_t smem_base = smem_to_u32(smem);
    const int tid = threadIdx.x;
    const int wid = tid >> 5;
    const int lid = tid & 31;
    const int bm = blockIdx.y * BM;
    const bool isKV = (mode == 1) && (blockIdx.x >= 16);
    const int bn = isKV ? (blockIdx.x - 16) * BN : blockIdx.x * BN;
    const __half* Bh = isKV ? B1 : B0;
    const float* bias = isKV ? bias1 : bias0;

    auto issue = [&](int c, int stage) {
        const __half* Asrc = (c >> 5) ? Alo : Ahi;
        const size_t k0 = (size_t)(c & 31) * BKH;
        const uint32_t sA = smem_base + stage * STG_BYTES;
        const uint32_t sB = sA + STG_A;
#pragma unroll
        for (int j = 0; j < 4; j++) {
            int seg = tid + j * 256;
            int r = seg >> 3, s = seg & 7;
            CP_ASYNC16(sA + r * APITCH_B + s * 16,
                       (const char*)(Asrc + (size_t)(bm + r) * HID_C + k0 + s * 8));
        }
#pragma unroll
        for (int j = 0; j < 4; j++) {
            int seg = tid + j * 256;
            int r = seg >> 3, s = seg & 7;
            CP_ASYNC16(sB + r * APITCH_B + s * 16,
                       (const char*)(Bh + (size_t)(bn + r) * HID_C + k0 + s * 8));
        }
    };

    float acc[4][4][4];
#pragma unroll
    for (int i = 0; i < 4; i++)
#pragma unroll
        for (int j = 0; j < 4; j++)
#pragma unroll
            for (int q = 0; q < 4; q++) acc[i][j][q] = 0.f;

    issue(0, 0); CP_COMMIT();
    issue(1, 1); CP_COMMIT();

    const int wm = (wid >> 2) * 64;
    const int wn = (wid & 3) * 32;
    const int mat = lid >> 3;
    const int wi = lid & 7;

    for (int t = 0; t < NCHUNK; t++) {
        CP_WAIT1();
        __syncthreads();
        if (t + 2 < NCHUNK) issue(t + 2, (t + 2) % NSTAGE);
        CP_COMMIT();

        const uint32_t aBase = smem_base + (t % NSTAGE) * STG_BYTES;
        const uint32_t bBase = aBase + STG_A;
#pragma unroll
        for (int ks = 0; ks < 4; ks++) {
            const int k0 = ks * 16;
            uint32_t afr[4][4];
            uint32_t bfr[4][2];
#pragma unroll
            for (int i = 0; i < 4; i++) {
                int row = wm + i * 16 + (mat & 1) * 8 + wi;
                int col = k0 + (mat >> 1) * 8;
                LDMATRIX_X4(afr[i][0], afr[i][1], afr[i][2], afr[i][3],
                            aBase + row * APITCH_B + col * 2);
            }
#pragma unroll
            for (int jj = 0; jj < 2; jj++) {
                int n = wn + jj * 16 + (mat >> 1) * 8 + wi;
                int k = k0 + (mat & 1) * 8;
                LDMATRIX_X4(bfr[2 * jj][0], bfr[2 * jj][1],
                            bfr[2 * jj + 1][0], bfr[2 * jj + 1][1],
                            bBase + n * APITCH_B + k * 2);
            }
#pragma unroll
            for (int i = 0; i < 4; i++)
#pragma unroll
                for (int j = 0; j < 4; j++)
                    MMA_F16(acc[i][j], afr[i], bfr[j]);
        }
    }

    const int g = lid >> 2;
    const int tq = lid & 3;
#pragma unroll
    for (int i = 0; i < 4; i++) {
#pragma unroll
        for (int j = 0; j < 4; j++) {
            int row0 = bm + wm + i * 16 + g;
            int col = bn + wn + j * 8 + tq * 2;
            float b0 = bias[col], b1 = bias[col + 1];
            float v00 = acc[i][j][0] + b0, v01 = acc[i][j][1] + b1;
            float v10 = acc[i][j][2] + b0, v11 = acc[i][j][3] + b1;
            if (mode == 0) {
                *(float2*)(C + (size_t)row0 * N + col) = make_float2(v00, v01);
                *(float2*)(C + (size_t)(row0 + 8) * N + col) = make_float2(v10, v11);
            } else if (!isKV) {   // Q: fold softmax scale (log2 domain), split
                v00 *= SOFTMAX_SCALE_LOG2; v01 *= SOFTMAX_SCALE_LOG2;
                v10 *= SOFTMAX_SCALE_LOG2; v11 *= SOFTMAX_SCALE_LOG2;
                uint32_t h, l;
                split2h(v00, v01, h, l);
                *(uint32_t*)&gQhi[(size_t)row0 * HID_C + col] = h;
                *(uint32_t*)&gQlo[(size_t)row0 * HID_C + col] = l;
                split2h(v10, v11, h, l);
                *(uint32_t*)&gQhi[(size_t)(row0 + 8) * HID_C + col] = h;
                *(uint32_t*)&gQlo[(size_t)(row0 + 8) * HID_C + col] = l;
            } else {
                if (bn == 0) {    // K: hi only
                    *(uint32_t*)&gKhi[(size_t)row0 * HEAD_D + col] =
                        pack2h(v00, v01);
                    *(uint32_t*)&gKhi[(size_t)(row0 + 8) * HEAD_D + col] =
                        pack2h(v10, v11);
                } else {          // V: transpose, hi only
                    int d0 = col - 128;
                    float vs[2][2] = {{v00, v01}, {v10, v11}};
#pragma unroll
                    for (int rr = 0; rr < 2; rr++)
#pragma unroll
                        for (int cc = 0; cc < 2; cc++)
                            gVthi[(size_t)(d0 + cc) * M_ROWS + row0 + rr * 8] =
                                __float2half_rn(vs[rr][cc]);
                }
            }
        }
    }
}

// ---------------------------------------------------------------------------
// Flash attention, tensor-core fp16; Q carries hi+lo, K/V/P hi only; causal.
// CTA: 128 q-rows x (head, batch); 8 warps (m16); KV tile FN=128.
// QK^T loads each K fragment once (round-10 MMA order); PV single-pass.
// ---------------------------------------------------------------------------
#define FM 128
#define FN 128
#define SMQ_HI 0
#define SMQ_LO 32768
#define SM_STG 65536
#define STGSZ 65536
#define SK_OFF 0
#define SV_OFF 32768
#define FA_SMEM (65536 + 2 * STGSZ)   /* 196608 */

__global__ __launch_bounds__(256, 1)
void flash_mma_kernel()
{
    extern __shared__ char sm[];
    const uint32_t sb = smem_to_u32(sm);
    const int tid = threadIdx.x;
    const int wid = tid >> 5;
    const int lid = tid & 31;
    const int qt = (int)gridDim.x - 1 - (int)blockIdx.x;  // heavy blocks first
    const int h = blockIdx.y;
    const int b = blockIdx.z;
    const int m0 = qt * FM;
    const int wm = wid * 16;
    const size_t bS = (size_t)b * S_LEN;
    const int g = lid >> 2, tq = lid & 3;
    const int ntiles = qt + 1;

    auto issueQ = [&]() {
#pragma unroll
        for (int j = 0; j < 16; j++) {
            int idx = tid + j * 256;
            int arr = idx >> 11;
            int rem = idx & 2047;
            int r = rem >> 4, c16 = rem & 15;
            const __half* src =
                (arr ? gQlo : gQhi) + (bS + m0 + r) * HID_C + h * HEAD_D + c16 * 8;
            CP_ASYNC16(sb + (arr ? SMQ_LO : SMQ_HI) + r * 256 + ((c16 ^ (r & 7)) << 4),
                       (const char*)src);
        }
    };
    auto issueKV = [&](int t, int s) {
        const uint32_t st = sb + SM_STG + s * STGSZ;
        const int n0 = t * FN;
#pragma unroll
        for (int j = 0; j < 8; j++) {
            int idx = tid + j * 256;
            int r = idx >> 4, c16 = idx & 15;
            const __half* src = gKhi + (bS + n0 + r) * HEAD_D + c16 * 8;
            CP_ASYNC16(st + SK_OFF + r * 256 + ((c16 ^ (r & 7)) << 4),
                       (const char*)src);
        }
#pragma unroll
        for (int j = 0; j < 8; j++) {
            int idx = tid + j * 256;
            int r = idx >> 4, c16 = idx & 15;
            const __half* src = gVthi + (size_t)r * M_ROWS + bS + n0 + c16 * 8;
            CP_ASYNC16(st + SV_OFF + r * 256 + ((c16 ^ (r & 7)) << 4),
                       (const char*)src);
        }
    };

    issueQ();
    issueKV(0, 0);
    CP_COMMIT();
    if (ntiles > 1) issueKV(1, 1);
    CP_COMMIT();
    CP_WAIT1();
    __syncthreads();

    float oacc[16][4];
#pragma unroll
    for (int i = 0; i < 16; i++)
#pragma unroll
        for (int q = 0; q < 4; q++) oacc[i][q] = 0.f;
    float mst[2] = {-1e30f, -1e30f};
    float lst[2] = {0.f, 0.f};

    const int mat = lid >> 3;
    const int wi = lid & 7;

    for (int t = 0; t < ntiles; t++) {
        const uint32_t st = sb + SM_STG + (t & 1) * STGSZ;

        // ---- S = (Qh + Ql) K^T : K fragments loaded once ----
        float sacc[16][4];
#pragma unroll
        for (int i = 0; i < 16; i++)
#pragma unroll
            for (int q = 0; q < 4; q++) sacc[i][q] = 0.f;

        {
            const uint32_t kb = st + SK_OFF;
#pragma unroll
            for (int kk = 0; kk < 8; kk++) {
                uint32_t ah[4], alq[4];
                {
                    int r = wm + (lid & 15);
                    int c16 = 2 * kk + (lid >> 4);
                    uint32_t off = r * 256 + ((c16 ^ (r & 7)) << 4);
                    LDMATRIX_X4(ah[0], ah[1], ah[2], ah[3], sb + SMQ_HI + off);
                    LDMATRIX_X4(alq[0], alq[1], alq[2], alq[3], sb + SMQ_LO + off);
                }
#pragma unroll
                for (int jj = 0; jj < 8; jj++) {
                    int r = jj * 16 + (mat >> 1) * 8 + wi;
                    int c16 = 2 * kk + (mat & 1);
                    uint32_t v[4];
                    LDMATRIX_X4(v[0], v[1], v[2], v[3],
                                kb + r * 256 + ((c16 ^ (r & 7)) << 4));
                    MMA_F16(sacc[2 * jj], ah, v);
                    MMA_F16(sacc[2 * jj], alq, v);
                    MMA_F16(sacc[2 * jj + 1], ah, (v + 2));
                    MMA_F16(sacc[2 * jj + 1], alq, (v + 2));
                }
            }
        }

        // ---- causal mask (diagonal tile only) ----
        if (t == qt) {
#pragma unroll
            for (int nb = 0; nb < 16; nb++)
#pragma unroll
                for (int q = 0; q < 4; q++) {
                    int col = t * FN + nb * 8 + tq * 2 + (q & 1);
                    int row = m0 + wm + g + (q >> 1) * 8;
                    if (col > row) sacc[nb][q] = -1e30f;
                }
        }

        // ---- online softmax (log2 domain) ----
#pragma unroll
        for (int hf = 0; hf < 2; hf++) {
            float tm = -1e30f;
#pragma unroll
            for (int nb = 0; nb < 16; nb++) {
                tm = fmaxf(tm, fmaxf(sacc[nb][2 * hf], sacc[nb][2 * hf + 1]));
            }
            tm = fmaxf(tm, __shfl_xor_sync(0xffffffffu, tm, 1));
            tm = fmaxf(tm, __shfl_xor_sync(0xffffffffu, tm, 2));
            float mn = fmaxf(mst[hf], tm);
            float corr = exp2f(mst[hf] - mn);
            mst[hf] = mn;
            float sum = 0.f;
#pragma unroll
            for (int nb = 0; nb < 16; nb++) {
#pragma unroll
                for (int e = 0; e < 2; e++) {
                    float p = exp2f(sacc[nb][2 * hf + e] - mn);
                    sacc[nb][2 * hf + e] = p;
                    sum += p;
                }
            }
            sum += __shfl_xor_sync(0xffffffffu, sum, 1);
            sum += __shfl_xor_sync(0xffffffffu, sum, 2);
            lst[hf] = lst[hf] * corr + sum;
#pragma unroll
            for (int nb = 0; nb < 16; nb++) {
                oacc[nb][2 * hf + 0] *= corr;
                oacc[nb][2 * hf + 1] *= corr;
            }
        }

        // ---- O += Ph Vh (single-pass PV; P rounded to fp16) ----
#pragma unroll
        for (int kk = 0; kk < 8; kk++) {
            uint32_t ah[4];
            ah[0] = pack2h(sacc[2 * kk][0], sacc[2 * kk][1]);
            ah[1] = pack2h(sacc[2 * kk][2], sacc[2 * kk][3]);
            ah[2] = pack2h(sacc[2 * kk + 1][0], sacc[2 * kk + 1][1]);
            ah[3] = pack2h(sacc[2 * kk + 1][2], sacc[2 * kk + 1][3]);
#pragma unroll
            for (int jj = 0; jj < 8; jj++) {
                int r = jj * 16 + (mat >> 1) * 8 + wi;
                int c16 = 2 * kk + (mat & 1);
                uint32_t v[4];
                LDMATRIX_X4(v[0], v[1], v[2], v[3],
                            st + SV_OFF + r * 256 + ((c16 ^ (r & 7)) << 4));
                MMA_F16(oacc[2 * jj], ah, v);
                MMA_F16(oacc[2 * jj + 1], ah, (v + 2));
            }
        }

        __syncthreads();
        if (t + 2 < ntiles) issueKV(t + 2, t & 1);
        CP_COMMIT();
        if (t + 1 < ntiles) {
            CP_WAIT1();
        } else {
            CP_WAIT0();
        }
        __syncthreads();
    }

    // ---- epilogue: O/l -> fp16 hi/lo into gA ----
#pragma unroll
    for (int hf = 0; hf < 2; hf++) {
        float inv = 1.f / lst[hf];
        size_t row = bS + m0 + wm + g + hf * 8;
#pragma unroll
        for (int nb = 0; nb < 16; nb++) {
            float v0 = oacc[nb][2 * hf] * inv;
            float v1 = oacc[nb][2 * hf + 1] * inv;
            uint32_t hh, ll;
            split2h(v0, v1, hh, ll);
            size_t off = row * HID_C + h * HEAD_D + nb * 8 + tq * 2;
            *(uint32_t*)&gA_hi[off] = hh;
            *(uint32_t*)&gA_lo[off] = ll;
        }
    }
}

// ---------------------------------------------------------------------------
extern "C" void kernel_launch(void* const* d_in, const int* in_sizes, int n_in,
                              void* d_out, int out_size)
{
    (void)in_sizes; (void)n_in; (void)out_size;
    const float* hs  = (const float*)d_in[0];
    /* d_in[1] = attention_mask (exact causal tril) applied analytically */
    const float* Wq  = (const float*)d_in[2];
    const float* bq  = (const float*)d_in[3];
    const float* Wkv = (const float*)d_in[4];
    const float* bkv = (const float*)d_in[5];
    const float* Wp  = (const float*)d_in[6];
    const float* bp  = (const float*)d_in[7];
    float* out = (float*)d_out;

    __half *pAhi, *pAlo, *pWqh, *pWkh, *pWph;
    cudaGetSymbolAddress((void**)&pAhi, gA_hi);
    cudaGetSymbolAddress((void**)&pAlo, gA_lo);
    cudaGetSymbolAddress((void**)&pWqh, gWq_hi);
    cudaGetSymbolAddress((void**)&pWkh, gWkv_hi);
    cudaGetSymbolAddress((void**)&pWph, gWp_hi);

    cudaFuncSetAttribute(mma_gemm_kernel,
                         cudaFuncAttributeMaxDynamicSharedMemorySize, GEMM_SMEM);
    cudaFuncSetAttribute(flash_mma_kernel,
                         cudaFuncAttributeMaxDynamicSharedMemorySize, FA_SMEM);

    // 1. split hidden states into fp16 hi/lo
    {
        int n4 = M_ROWS * HID_C / 4;
        split_f32_kernel<<<(n4 + 255) / 256, 256>>>(hs, pAhi, pAlo, n4);
    }
    // 2. fused transpose+convert of all three weights
    tconv_all_kernel<<<dim3(HID_C / 32, HID_C / 32, 3), dim3(32, 8)>>>(Wq, Wp, Wkv);

    // 3. fused Q + KV projection (grid.x: 16 Q blocks + 2 KV blocks)
    mma_gemm_kernel<<<dim3(18, M_ROWS / BM), 256, GEMM_SMEM>>>(
        pAhi, pAlo, pWqh, bq, pWkh, bkv, nullptr, HID_C, 1);
    // 4. attention -> gA_hi/gA_lo
    flash_mma_kernel<<<dim3(S_LEN / FM, N_HEADS, B_SZ), 256, FA_SMEM>>>();
    // 5. out = attn @ Wp + bp
    mma_gemm_kernel<<<dim3(16, M_ROWS / BM), 256, GEMM_SMEM>>>(
        pAhi, pAlo, pWph, bp, nullptr, nullptr, out, HID_C, 0);
}

// round 13
// speedup vs baseline: 1.8445x; 1.2094x over previous
#include <cuda_runtime.h>
#include <cuda_fp16.h>
#include <cstdint>

#define B_SZ 2
#define S_LEN 2048
#define HID_C 2048
#define N_HEADS 16
#define HEAD_D 128
#define M_ROWS (B_SZ * S_LEN)   /* 4096 */
#define KV_C 256

#define SOFTMAX_SCALE_LOG2 0.12754404735576283f       /* 1/sqrt(128)*log2(e) */

// ---------------------------------------------------------------------------
// Device-global scratch (allocation-free rule)
// ---------------------------------------------------------------------------
__device__ __half gA_hi[(size_t)M_ROWS * HID_C];   // hs / attn hi (left operand)
__device__ __half gA_lo[(size_t)M_ROWS * HID_C];
__device__ __half gQhi[(size_t)M_ROWS * HID_C];    // pre-scaled by 1/sqrt(d)*log2e
__device__ __half gQlo[(size_t)M_ROWS * HID_C];
__device__ __half gKhi[(size_t)M_ROWS * HEAD_D];          // right operand: hi only
__device__ __half gVthi[(size_t)HEAD_D * M_ROWS];         // V^T [d][bS], hi only
__device__ __half gWq_hi[(size_t)HID_C * HID_C];
__device__ __half gWkv_hi[(size_t)KV_C * HID_C];
__device__ __half gWp_hi[(size_t)HID_C * HID_C];

__device__ __forceinline__ uint32_t smem_to_u32(const void* p) {
    uint32_t a;
    asm("{ .reg .u64 t; cvta.to.shared.u64 t, %1; cvt.u32.u64 %0, t; }"
        : "=r"(a) : "l"(p));
    return a;
}

#define CP_ASYNC16(sm, g) \
    asm volatile("cp.async.cg.shared.global [%0], [%1], 16;" \
                 :: "r"(sm), "l"(g) : "memory")
#define CP_COMMIT() asm volatile("cp.async.commit_group;" ::: "memory")
#define CP_WAIT1()  asm volatile("cp.async.wait_group 1;" ::: "memory")
#define CP_WAIT0()  asm volatile("cp.async.wait_group 0;" ::: "memory")

#define LDMATRIX_X4(r0, r1, r2, r3, addr) \
    asm volatile("ldmatrix.sync.aligned.m8n8.x4.shared.b16 {%0,%1,%2,%3}, [%4];" \
                 : "=r"(r0), "=r"(r1), "=r"(r2), "=r"(r3) : "r"(addr))

#define MMA_F16(d, a, b) \
    asm volatile("mma.sync.aligned.m16n8k16.row.col.f32.f16.f16.f32 " \
                 "{%0,%1,%2,%3}, {%4,%5,%6,%7}, {%8,%9}, {%0,%1,%2,%3};" \
                 : "+f"((d)[0]), "+f"((d)[1]), "+f"((d)[2]), "+f"((d)[3]) \
                 : "r"((a)[0]), "r"((a)[1]), "r"((a)[2]), "r"((a)[3]), \
                   "r"((b)[0]), "r"((b)[1]))

__device__ __forceinline__ uint32_t pack_h2(__half x, __half y) {
    __half2 t; t.x = x; t.y = y;
    return *reinterpret_cast<uint32_t*>(&t);
}
// fp32 pair -> fp16 hi + fp16 lo(residual)
__device__ __forceinline__ void split2h(float v0, float v1,
                                        uint32_t& hi, uint32_t& lo) {
    __half h0 = __float2half_rn(v0);
    __half h1 = __float2half_rn(v1);
    hi = pack_h2(h0, h1);
    lo = pack_h2(__float2half_rn(v0 - __half2float(h0)),
                 __float2half_rn(v1 - __half2float(h1)));
}
__device__ __forceinline__ uint32_t pack2h(float v0, float v1) {
    __half2 t = __floats2half2_rn(v0, v1);
    return *reinterpret_cast<uint32_t*>(&t);
}

// ---------------------------------------------------------------------------
// fp32 -> (hi, lo) fp16 split, elementwise
// ---------------------------------------------------------------------------
__global__ void split_f32_kernel(const float* __restrict__ src,
                                 __half* __restrict__ hi,
                                 __half* __restrict__ lo, int n4)
{
    int i = blockIdx.x * blockDim.x + threadIdx.x;
    if (i >= n4) return;
    float4 v = ((const float4*)src)[i];
    uint32_t h0, l0, h1, l1;
    split2h(v.x, v.y, h0, l0);
    split2h(v.z, v.w, h1, l1);
    ((uint32_t*)hi)[2 * i] = h0;
    ((uint32_t*)hi)[2 * i + 1] = h1;
    ((uint32_t*)lo)[2 * i] = l0;
    ((uint32_t*)lo)[2 * i + 1] = l1;
}

// ---------------------------------------------------------------------------
// Fused weight transpose+convert: z=0 Wq, z=1 Wp, z=2 Wkv
// ---------------------------------------------------------------------------
__global__ void tconv_all_kernel(const float* __restrict__ Wq,
                                 const float* __restrict__ Wp,
                                 const float* __restrict__ Wkv)
{
    const int z = blockIdx.z;
    const float* W = (z == 0) ? Wq : (z == 1) ? Wp : Wkv;
    __half* T = (z == 0) ? gWq_hi : (z == 1) ? gWp_hi : gWkv_hi;
    const int N = (z == 2) ? KV_C : HID_C;
    if (blockIdx.x * 32 >= N) return;

    __shared__ float tile[32][33];
    int n0 = blockIdx.x * 32, k0 = blockIdx.y * 32;
    int tx = threadIdx.x, ty = threadIdx.y;
#pragma unroll
    for (int j = 0; j < 32; j += 8)
        tile[ty + j][tx] = W[(size_t)(k0 + ty + j) * N + n0 + tx];
    __syncthreads();
#pragma unroll
    for (int j = 0; j < 32; j += 8)
        T[(size_t)(n0 + ty + j) * HID_C + k0 + tx] =
            __float2half_rn(tile[tx][ty + j]);
}

// ---------------------------------------------------------------------------
// mma.sync fp16 GEMM: C = (Ah[+Al]) @ Bh^T + bias
// K-chunk = 64 halves (128B/row, pitch 144 -> conflict-free ldmatrix)
// 256 threads, 8 warps (2x4), warp tile 64x32, 3-stage cp.async, 2 CTA/SM.
// mode 0: out-proj -> fp32 C (B0 = Wp), SINGLE product (Ah only, 32 chunks)
// mode 1: fused QKV (2-product, 64 chunks):
//         bx<16 -> Q (B0=Wq) scaled+split -> gQhi/gQlo
//         bx>=16 -> KV (B1=Wkv): bn==0 -> K hi; bn==128 -> V^T hi
// ---------------------------------------------------------------------------
#define BM 128
#define BN 128
#define BKH 64                  /* halves per chunk */
#define APITCH_B 144            /* 128B data + 16B pad */
#define STG_A (BM * APITCH_B)   /* 18432 */
#define STG_B (BN * APITCH_B)
#define STG_BYTES (STG_A + STG_B)  /* 36864 */
#define NSTAGE 3
#define GEMM_SMEM (NSTAGE * STG_BYTES)  /* 110592 */

__global__ __launch_bounds__(256, 2)
void mma_gemm_kernel(const __half* __restrict__ Ahi,
                     const __half* __restrict__ Alo,
                     const __half* __restrict__ B0,
                     const float* __restrict__ bias0,
                     const __half* __restrict__ B1,
                     const float* __restrict__ bias1,
                     float* __restrict__ C, int N, int mode)
{
    extern __shared__ char smem[];
    const uint32_t smem_base = smem_to_u32(smem);
    const int tid = threadIdx.x;
    const int wid = tid >> 5;
    const int lid = tid & 31;
    const int bm = blockIdx.y * BM;
    const bool isKV = (mode == 1) && (blockIdx.x >= 16);
    const int bn = isKV ? (blockIdx.x - 16) * BN : blockIdx.x * BN;
    const __half* Bh = isKV ? B1 : B0;
    const float* bias = isKV ? bias1 : bias0;
    const int nchunk = (mode == 0) ? 32 : 64;   /* 1 or 2 emulation phases */

    auto issue = [&](int c, int stage) {
        const __half* Asrc = (c >> 5) ? Alo : Ahi;
        const size_t k0 = (size_t)(c & 31) * BKH;
        const uint32_t sA = smem_base + stage * STG_BYTES;
        const uint32_t sB = sA + STG_A;
#pragma unroll
        for (int j = 0; j < 4; j++) {
            int seg = tid + j * 256;
            int r = seg >> 3, s = seg & 7;
            CP_ASYNC16(sA + r * APITCH_B + s * 16,
                       (const char*)(Asrc + (size_t)(bm + r) * HID_C + k0 + s * 8));
        }
#pragma unroll
        for (int j = 0; j < 4; j++) {
            int seg = tid + j * 256;
            int r = seg >> 3, s = seg & 7;
            CP_ASYNC16(sB + r * APITCH_B + s * 16,
                       (const char*)(Bh + (size_t)(bn + r) * HID_C + k0 + s * 8));
        }
    };

    float acc[4][4][4];
#pragma unroll
    for (int i = 0; i < 4; i++)
#pragma unroll
        for (int j = 0; j < 4; j++)
#pragma unroll
            for (int q = 0; q < 4; q++) acc[i][j][q] = 0.f;

    issue(0, 0); CP_COMMIT();
    issue(1, 1); CP_COMMIT();

    const int wm = (wid >> 2) * 64;
    const int wn = (wid & 3) * 32;
    const int mat = lid >> 3;
    const int wi = lid & 7;

    for (int t = 0; t < nchunk; t++) {
        CP_WAIT1();
        __syncthreads();
        if (t + 2 < nchunk) issue(t + 2, (t + 2) % NSTAGE);
        CP_COMMIT();

        const uint32_t aBase = smem_base + (t % NSTAGE) * STG_BYTES;
        const uint32_t bBase = aBase + STG_A;
#pragma unroll
        for (int ks = 0; ks < 4; ks++) {
            const int k0 = ks * 16;
            uint32_t afr[4][4];
            uint32_t bfr[4][2];
#pragma unroll
            for (int i = 0; i < 4; i++) {
                int row = wm + i * 16 + (mat & 1) * 8 + wi;
                int col = k0 + (mat >> 1) * 8;
                LDMATRIX_X4(afr[i][0], afr[i][1], afr[i][2], afr[i][3],
                            aBase + row * APITCH_B + col * 2);
            }
#pragma unroll
            for (int jj = 0; jj < 2; jj++) {
                int n = wn + jj * 16 + (mat >> 1) * 8 + wi;
                int k = k0 + (mat & 1) * 8;
                LDMATRIX_X4(bfr[2 * jj][0], bfr[2 * jj][1],
                            bfr[2 * jj + 1][0], bfr[2 * jj + 1][1],
                            bBase + n * APITCH_B + k * 2);
            }
#pragma unroll
            for (int i = 0; i < 4; i++)
#pragma unroll
                for (int j = 0; j < 4; j++)
                    MMA_F16(acc[i][j], afr[i], bfr[j]);
        }
    }

    const int g = lid >> 2;
    const int tq = lid & 3;
#pragma unroll
    for (int i = 0; i < 4; i++) {
#pragma unroll
        for (int j = 0; j < 4; j++) {
            int row0 = bm + wm + i * 16 + g;
            int col = bn + wn + j * 8 + tq * 2;
            float b0 = bias[col], b1 = bias[col + 1];
            float v00 = acc[i][j][0] + b0, v01 = acc[i][j][1] + b1;
            float v10 = acc[i][j][2] + b0, v11 = acc[i][j][3] + b1;
            if (mode == 0) {
                *(float2*)(C + (size_t)row0 * N + col) = make_float2(v00, v01);
                *(float2*)(C + (size_t)(row0 + 8) * N + col) = make_float2(v10, v11);
            } else if (!isKV) {   // Q: fold softmax scale (log2 domain), split
                v00 *= SOFTMAX_SCALE_LOG2; v01 *= SOFTMAX_SCALE_LOG2;
                v10 *= SOFTMAX_SCALE_LOG2; v11 *= SOFTMAX_SCALE_LOG2;
                uint32_t h, l;
                split2h(v00, v01, h, l);
                *(uint32_t*)&gQhi[(size_t)row0 * HID_C + col] = h;
                *(uint32_t*)&gQlo[(size_t)row0 * HID_C + col] = l;
                split2h(v10, v11, h, l);
                *(uint32_t*)&gQhi[(size_t)(row0 + 8) * HID_C + col] = h;
                *(uint32_t*)&gQlo[(size_t)(row0 + 8) * HID_C + col] = l;
            } else {
                if (bn == 0) {    // K: hi only
                    *(uint32_t*)&gKhi[(size_t)row0 * HEAD_D + col] =
                        pack2h(v00, v01);
                    *(uint32_t*)&gKhi[(size_t)(row0 + 8) * HEAD_D + col] =
                        pack2h(v10, v11);
                } else {          // V: transpose, hi only
                    int d0 = col - 128;
                    float vs[2][2] = {{v00, v01}, {v10, v11}};
#pragma unroll
                    for (int rr = 0; rr < 2; rr++)
#pragma unroll
                        for (int cc = 0; cc < 2; cc++)
                            gVthi[(size_t)(d0 + cc) * M_ROWS + row0 + rr * 8] =
                                __float2half_rn(vs[rr][cc]);
                }
            }
        }
    }
}

// ---------------------------------------------------------------------------
// Flash attention, tensor-core fp16; Q carries hi+lo, K/V/P hi only; causal.
// CTA: 128 q-rows x (head, batch); 8 warps (m16); KV tile FN=128.
// QK^T loads each K fragment once; PV single-pass (P rounded to fp16).
// ---------------------------------------------------------------------------
#define FM 128
#define FN 128
#define SMQ_HI 0
#define SMQ_LO 32768
#define SM_STG 65536
#define STGSZ 65536
#define SK_OFF 0
#define SV_OFF 32768
#define FA_SMEM (65536 + 2 * STGSZ)   /* 196608 */

__global__ __launch_bounds__(256, 1)
void flash_mma_kernel()
{
    extern __shared__ char sm[];
    const uint32_t sb = smem_to_u32(sm);
    const int tid = threadIdx.x;
    const int wid = tid >> 5;
    const int lid = tid & 31;
    const int qt = (int)gridDim.x - 1 - (int)blockIdx.x;  // heavy blocks first
    const int h = blockIdx.y;
    const int b = blockIdx.z;
    const int m0 = qt * FM;
    const int wm = wid * 16;
    const size_t bS = (size_t)b * S_LEN;
    const int g = lid >> 2, tq = lid & 3;
    const int ntiles = qt + 1;

    auto issueQ = [&]() {
#pragma unroll
        for (int j = 0; j < 16; j++) {
            int idx = tid + j * 256;
            int arr = idx >> 11;
            int rem = idx & 2047;
            int r = rem >> 4, c16 = rem & 15;
            const __half* src =
                (arr ? gQlo : gQhi) + (bS + m0 + r) * HID_C + h * HEAD_D + c16 * 8;
            CP_ASYNC16(sb + (arr ? SMQ_LO : SMQ_HI) + r * 256 + ((c16 ^ (r & 7)) << 4),
                       (const char*)src);
        }
    };
    auto issueKV = [&](int t, int s) {
        const uint32_t st = sb + SM_STG + s * STGSZ;
        const int n0 = t * FN;
#pragma unroll
        for (int j = 0; j < 8; j++) {
            int idx = tid + j * 256;
            int r = idx >> 4, c16 = idx & 15;
            const __half* src = gKhi + (bS + n0 + r) * HEAD_D + c16 * 8;
            CP_ASYNC16(st + SK_OFF + r * 256 + ((c16 ^ (r & 7)) << 4),
                       (const char*)src);
        }
#pragma unroll
        for (int j = 0; j < 8; j++) {
            int idx = tid + j * 256;
            int r = idx >> 4, c16 = idx & 15;
            const __half* src = gVthi + (size_t)r * M_ROWS + bS + n0 + c16 * 8;
            CP_ASYNC16(st + SV_OFF + r * 256 + ((c16 ^ (r & 7)) << 4),
                       (const char*)src);
        }
    };

    issueQ();
    issueKV(0, 0);
    CP_COMMIT();
    if (ntiles > 1) issueKV(1, 1);
    CP_COMMIT();
    CP_WAIT1();
    __syncthreads();

    float oacc[16][4];
#pragma unroll
    for (int i = 0; i < 16; i++)
#pragma unroll
        for (int q = 0; q < 4; q++) oacc[i][q] = 0.f;
    float mst[2] = {-1e30f, -1e30f};
    float lst[2] = {0.f, 0.f};

    const int mat = lid >> 3;
    const int wi = lid & 7;

    for (int t = 0; t < ntiles; t++) {
        const uint32_t st = sb + SM_STG + (t & 1) * STGSZ;

        // ---- S = (Qh + Ql) K^T : K fragments loaded once ----
        float sacc[16][4];
#pragma unroll
        for (int i = 0; i < 16; i++)
#pragma unroll
            for (int q = 0; q < 4; q++) sacc[i][q] = 0.f;

        {
            const uint32_t kb = st + SK_OFF;
#pragma unroll
            for (int kk = 0; kk < 8; kk++) {
                uint32_t ah[4], alq[4];
                {
                    int r = wm + (lid & 15);
                    int c16 = 2 * kk + (lid >> 4);
                    uint32_t off = r * 256 + ((c16 ^ (r & 7)) << 4);
                    LDMATRIX_X4(ah[0], ah[1], ah[2], ah[3], sb + SMQ_HI + off);
                    LDMATRIX_X4(alq[0], alq[1], alq[2], alq[3], sb + SMQ_LO + off);
                }
#pragma unroll
                for (int jj = 0; jj < 8; jj++) {
                    int r = jj * 16 + (mat >> 1) * 8 + wi;
                    int c16 = 2 * kk + (mat & 1);
                    uint32_t v[4];
                    LDMATRIX_X4(v[0], v[1], v[2], v[3],
                                kb + r * 256 + ((c16 ^ (r & 7)) << 4));
                    MMA_F16(sacc[2 * jj], ah, v);
                    MMA_F16(sacc[2 * jj], alq, v);
                    MMA_F16(sacc[2 * jj + 1], ah, (v + 2));
                    MMA_F16(sacc[2 * jj + 1], alq, (v + 2));
                }
            }
        }

        // ---- causal mask (diagonal tile only) ----
        if (t == qt) {
#pragma unroll
            for (int nb = 0; nb < 16; nb++)
#pragma unroll
                for (int q = 0; q < 4; q++) {
                    int col = t * FN + nb * 8 + tq * 2 + (q & 1);
                    int row = m0 + wm + g + (q >> 1) * 8;
                    if (col > row) sacc[nb][q] = -1e30f;
                }
        }

        // ---- online softmax (log2 domain) ----
#pragma unroll
        for (int hf = 0; hf < 2; hf++) {
            float tm = -1e30f;
#pragma unroll
            for (int nb = 0; nb < 16; nb++) {
                tm = fmaxf(tm, fmaxf(sacc[nb][2 * hf], sacc[nb][2 * hf + 1]));
            }
            tm = fmaxf(tm, __shfl_xor_sync(0xffffffffu, tm, 1));
            tm = fmaxf(tm, __shfl_xor_sync(0xffffffffu, tm, 2));
            float mn = fmaxf(mst[hf], tm);
            float corr = exp2f(mst[hf] - mn);
            mst[hf] = mn;
            float sum = 0.f;
#pragma unroll
            for (int nb = 0; nb < 16; nb++) {
#pragma unroll
                for (int e = 0; e < 2; e++) {
                    float p = exp2f(sacc[nb][2 * hf + e] - mn);
                    sacc[nb][2 * hf + e] = p;
                    sum += p;
                }
            }
            sum += __shfl_xor_sync(0xffffffffu, sum, 1);
            sum += __shfl_xor_sync(0xffffffffu, sum, 2);
            lst[hf] = lst[hf] * corr + sum;
#pragma unroll
            for (int nb = 0; nb < 16; nb++) {
                oacc[nb][2 * hf + 0] *= corr;
                oacc[nb][2 * hf + 1] *= corr;
            }
        }

        // ---- O += Ph Vh (single-pass PV; P rounded to fp16) ----
#pragma unroll
        for (int kk = 0; kk < 8; kk++) {
            uint32_t ah[4];
            ah[0] = pack2h(sacc[2 * kk][0], sacc[2 * kk][1]);
            ah[1] = pack2h(sacc[2 * kk][2], sacc[2 * kk][3]);
            ah[2] = pack2h(sacc[2 * kk + 1][0], sacc[2 * kk + 1][1]);
            ah[3] = pack2h(sacc[2 * kk + 1][2], sacc[2 * kk + 1][3]);
#pragma unroll
            for (int jj = 0; jj < 8; jj++) {
                int r = jj * 16 + (mat >> 1) * 8 + wi;
                int c16 = 2 * kk + (mat & 1);
                uint32_t v[4];
                LDMATRIX_X4(v[0], v[1], v[2], v[3],
                            st + SV_OFF + r * 256 + ((c16 ^ (r & 7)) << 4));
                MMA_F16(oacc[2 * jj], ah, v);
                MMA_F16(oacc[2 * jj + 1], ah, (v + 2));
            }
        }

        __syncthreads();
        if (t + 2 < ntiles) issueKV(t + 2, t & 1);
        CP_COMMIT();
        if (t + 1 < ntiles) {
            CP_WAIT1();
        } else {
            CP_WAIT0();
        }
        __syncthreads();
    }

    // ---- epilogue: O/l -> fp16 hi into gA (out-proj is single-product now,
    //      but keep hi/lo writes so layout stays identical; lo unused cost ~0)
#pragma unroll
    for (int hf = 0; hf < 2; hf++) {
        float inv = 1.f / lst[hf];
        size_t row = bS + m0 + wm + g + hf * 8;
#pragma unroll
        for (int nb = 0; nb < 16; nb++) {
            float v0 = oacc[nb][2 * hf] * inv;
            float v1 = oacc[nb][2 * hf + 1] * inv;
            size_t off = row * HID_C + h * HEAD_D + nb * 8 + tq * 2;
            *(uint32_t*)&gA_hi[off] = pack2h(v0, v1);
        }
    }
}

// ---------------------------------------------------------------------------
extern "C" void kernel_launch(void* const* d_in, const int* in_sizes, int n_in,
                              void* d_out, int out_size)
{
    (void)in_sizes; (void)n_in; (void)out_size;
    const float* hs  = (const float*)d_in[0];
    /* d_in[1] = attention_mask (exact causal tril) applied analytically */
    const float* Wq  = (const float*)d_in[2];
    const float* bq  = (const float*)d_in[3];
    const float* Wkv = (const float*)d_in[4];
    const float* bkv = (const float*)d_in[5];
    const float* Wp  = (const float*)d_in[6];
    const float* bp  = (const float*)d_in[7];
    float* out = (float*)d_out;

    __half *pAhi, *pAlo, *pWqh, *pWkh, *pWph;
    cudaGetSymbolAddress((void**)&pAhi, gA_hi);
    cudaGetSymbolAddress((void**)&pAlo, gA_lo);
    cudaGetSymbolAddress((void**)&pWqh, gWq_hi);
    cudaGetSymbolAddress((void**)&pWkh, gWkv_hi);
    cudaGetSymbolAddress((void**)&pWph, gWp_hi);

    cudaFuncSetAttribute(mma_gemm_kernel,
                         cudaFuncAttributeMaxDynamicSharedMemorySize, GEMM_SMEM);
    cudaFuncSetAttribute(flash_mma_kernel,
                         cudaFuncAttributeMaxDynamicSharedMemorySize, FA_SMEM);

    // 1. split hidden states into fp16 hi/lo
    {
        int n4 = M_ROWS * HID_C / 4;
        split_f32_kernel<<<(n4 + 255) / 256, 256>>>(hs, pAhi, pAlo, n4);
    }
    // 2. fused transpose+convert of all three weights
    tconv_all_kernel<<<dim3(HID_C / 32, HID_C / 32, 3), dim3(32, 8)>>>(Wq, Wp, Wkv);

    // 3. fused Q + KV projection (grid.x: 16 Q blocks + 2 KV blocks; 2-product)
    mma_gemm_kernel<<<dim3(18, M_ROWS / BM), 256, GEMM_SMEM>>>(
        pAhi, pAlo, pWqh, bq, pWkh, bkv, nullptr, HID_C, 1);
    // 4. attention -> gA_hi (fp16)
    flash_mma_kernel<<<dim3(S_LEN / FM, N_HEADS, B_SZ), 256, FA_SMEM>>>();
    // 5. out = attn @ Wp + bp (single-product: attn rounded to fp16)
    mma_gemm_kernel<<<dim3(16, M_ROWS / BM), 256, GEMM_SMEM>>>(
        pAhi, pAlo, pWph, bp, nullptr, nullptr, out, HID_C, 0);
}

// round 14
// speedup vs baseline: 2.3073x; 1.2509x over previous
#include <cuda_runtime.h>
#include <cuda_fp16.h>
#include <cstdint>

#define B_SZ 2
#define S_LEN 2048
#define HID_C 2048
#define N_HEADS 16
#define HEAD_D 128
#define M_ROWS (B_SZ * S_LEN)   /* 4096 */
#define KV_C 256

#define SOFTMAX_SCALE_LOG2 0.12754404735576283f       /* 1/sqrt(128)*log2(e) */

// ---------------------------------------------------------------------------
// Device-global scratch (allocation-free rule)
// ---------------------------------------------------------------------------
__device__ __half gA_hi[(size_t)M_ROWS * HID_C];   // hs / attn (fp16, left operand)
__device__ __half gQhi[(size_t)M_ROWS * HID_C];    // pre-scaled by 1/sqrt(d)*log2e
__device__ __half gQlo[(size_t)M_ROWS * HID_C];    // Q residual (from fp32 accum)
__device__ __half gKhi[(size_t)M_ROWS * HEAD_D];          // right operand: hi only
__device__ __half gVthi[(size_t)HEAD_D * M_ROWS];         // V^T [d][bS], hi only
__device__ __half gWq_hi[(size_t)HID_C * HID_C];
__device__ __half gWkv_hi[(size_t)KV_C * HID_C];
__device__ __half gWp_hi[(size_t)HID_C * HID_C];

__device__ __forceinline__ uint32_t smem_to_u32(const void* p) {
    uint32_t a;
    asm("{ .reg .u64 t; cvta.to.shared.u64 t, %1; cvt.u32.u64 %0, t; }"
        : "=r"(a) : "l"(p));
    return a;
}

#define CP_ASYNC16(sm, g) \
    asm volatile("cp.async.cg.shared.global [%0], [%1], 16;" \
                 :: "r"(sm), "l"(g) : "memory")
#define CP_COMMIT() asm volatile("cp.async.commit_group;" ::: "memory")
#define CP_WAIT1()  asm volatile("cp.async.wait_group 1;" ::: "memory")
#define CP_WAIT0()  asm volatile("cp.async.wait_group 0;" ::: "memory")

#define LDMATRIX_X4(r0, r1, r2, r3, addr) \
    asm volatile("ldmatrix.sync.aligned.m8n8.x4.shared.b16 {%0,%1,%2,%3}, [%4];" \
                 : "=r"(r0), "=r"(r1), "=r"(r2), "=r"(r3) : "r"(addr))

#define MMA_F16(d, a, b) \
    asm volatile("mma.sync.aligned.m16n8k16.row.col.f32.f16.f16.f32 " \
                 "{%0,%1,%2,%3}, {%4,%5,%6,%7}, {%8,%9}, {%0,%1,%2,%3};" \
                 : "+f"((d)[0]), "+f"((d)[1]), "+f"((d)[2]), "+f"((d)[3]) \
                 : "r"((a)[0]), "r"((a)[1]), "r"((a)[2]), "r"((a)[3]), \
                   "r"((b)[0]), "r"((b)[1]))

__device__ __forceinline__ uint32_t pack_h2(__half x, __half y) {
    __half2 t; t.x = x; t.y = y;
    return *reinterpret_cast<uint32_t*>(&t);
}
// fp32 pair -> fp16 hi + fp16 lo(residual)
__device__ __forceinline__ void split2h(float v0, float v1,
                                        uint32_t& hi, uint32_t& lo) {
    __half h0 = __float2half_rn(v0);
    __half h1 = __float2half_rn(v1);
    hi = pack_h2(h0, h1);
    lo = pack_h2(__float2half_rn(v0 - __half2float(h0)),
                 __float2half_rn(v1 - __half2float(h1)));
}
__device__ __forceinline__ uint32_t pack2h(float v0, float v1) {
    __half2 t = __floats2half2_rn(v0, v1);
    return *reinterpret_cast<uint32_t*>(&t);
}

// ---------------------------------------------------------------------------
// fp32 -> fp16 convert (hi only; hs is consumed in fp16 now)
// ---------------------------------------------------------------------------
__global__ void conv_f32_kernel(const float* __restrict__ src,
                                __half* __restrict__ hi, int n4)
{
    int i = blockIdx.x * blockDim.x + threadIdx.x;
    if (i >= n4) return;
    float4 v = ((const float4*)src)[i];
    ((uint32_t*)hi)[2 * i] = pack2h(v.x, v.y);
    ((uint32_t*)hi)[2 * i + 1] = pack2h(v.z, v.w);
}

// ---------------------------------------------------------------------------
// Fused weight transpose+convert: z=0 Wq, z=1 Wp, z=2 Wkv
// ---------------------------------------------------------------------------
__global__ void tconv_all_kernel(const float* __restrict__ Wq,
                                 const float* __restrict__ Wp,
                                 const float* __restrict__ Wkv)
{
    const int z = blockIdx.z;
    const float* W = (z == 0) ? Wq : (z == 1) ? Wp : Wkv;
    __half* T = (z == 0) ? gWq_hi : (z == 1) ? gWp_hi : gWkv_hi;
    const int N = (z == 2) ? KV_C : HID_C;
    if (blockIdx.x * 32 >= N) return;

    __shared__ float tile[32][33];
    int n0 = blockIdx.x * 32, k0 = blockIdx.y * 32;
    int tx = threadIdx.x, ty = threadIdx.y;
#pragma unroll
    for (int j = 0; j < 32; j += 8)
        tile[ty + j][tx] = W[(size_t)(k0 + ty + j) * N + n0 + tx];
    __syncthreads();
#pragma unroll
    for (int j = 0; j < 32; j += 8)
        T[(size_t)(n0 + ty + j) * HID_C + k0 + tx] =
            __float2half_rn(tile[tx][ty + j]);
}

// ---------------------------------------------------------------------------
// mma.sync fp16 GEMM: C = Ah @ Bh^T + bias  (single product, 32 chunks)
// K-chunk = 64 halves (128B/row, pitch 144 -> conflict-free ldmatrix)
// 256 threads, 8 warps (2x4), warp tile 64x32, 3-stage cp.async, 2 CTA/SM.
// mode 0: out-proj -> fp32 C (B0 = Wp)
// mode 1: fused QKV: bx<16 -> Q (B0=Wq) scaled + split(fp32 accum) -> gQhi/gQlo
//                    bx>=16 -> KV (B1=Wkv): bn==0 -> K hi; bn==128 -> V^T hi
// ---------------------------------------------------------------------------
#define BM 128
#define BN 128
#define BKH 64                  /* halves per chunk */
#define APITCH_B 144            /* 128B data + 16B pad */
#define STG_A (BM * APITCH_B)   /* 18432 */
#define STG_B (BN * APITCH_B)
#define STG_BYTES (STG_A + STG_B)  /* 36864 */
#define NSTAGE 3
#define GEMM_SMEM (NSTAGE * STG_BYTES)  /* 110592 */
#define NCHUNK 32               /* single emulation phase */

__global__ __launch_bounds__(256, 2)
void mma_gemm_kernel(const __half* __restrict__ Ahi,
                     const __half* __restrict__ B0,
                     const float* __restrict__ bias0,
                     const __half* __restrict__ B1,
                     const float* __restrict__ bias1,
                     float* __restrict__ C, int N, int mode)
{
    extern __shared__ char smem[];
    const uint32_t smem_base = smem_to_u32(smem);
    const int tid = threadIdx.x;
    const int wid = tid >> 5;
    const int lid = tid & 31;
    const int bm = blockIdx.y * BM;
    const bool isKV = (mode == 1) && (blockIdx.x >= 16);
    const int bn = isKV ? (blockIdx.x - 16) * BN : blockIdx.x * BN;
    const __half* Bh = isKV ? B1 : B0;
    const float* bias = isKV ? bias1 : bias0;

    auto issue = [&](int c, int stage) {
        const size_t k0 = (size_t)c * BKH;
        const uint32_t sA = smem_base + stage * STG_BYTES;
        const uint32_t sB = sA + STG_A;
#pragma unroll
        for (int j = 0; j < 4; j++) {
            int seg = tid + j * 256;
            int r = seg >> 3, s = seg & 7;
            CP_ASYNC16(sA + r * APITCH_B + s * 16,
                       (const char*)(Ahi + (size_t)(bm + r) * HID_C + k0 + s * 8));
        }
#pragma unroll
        for (int j = 0; j < 4; j++) {
            int seg = tid + j * 256;
            int r = seg >> 3, s = seg & 7;
            CP_ASYNC16(sB + r * APITCH_B + s * 16,
                       (const char*)(Bh + (size_t)(bn + r) * HID_C + k0 + s * 8));
        }
    };

    float acc[4][4][4];
#pragma unroll
    for (int i = 0; i < 4; i++)
#pragma unroll
        for (int j = 0; j < 4; j++)
#pragma unroll
            for (int q = 0; q < 4; q++) acc[i][j][q] = 0.f;

    issue(0, 0); CP_COMMIT();
    issue(1, 1); CP_COMMIT();

    const int wm = (wid >> 2) * 64;
    const int wn = (wid & 3) * 32;
    const int mat = lid >> 3;
    const int wi = lid & 7;

    for (int t = 0; t < NCHUNK; t++) {
        CP_WAIT1();
        __syncthreads();
        if (t + 2 < NCHUNK) issue(t + 2, (t + 2) % NSTAGE);
        CP_COMMIT();

        const uint32_t aBase = smem_base + (t % NSTAGE) * STG_BYTES;
        const uint32_t bBase = aBase + STG_A;
#pragma unroll
        for (int ks = 0; ks < 4; ks++) {
            const int k0 = ks * 16;
            uint32_t afr[4][4];
            uint32_t bfr[4][2];
#pragma unroll
            for (int i = 0; i < 4; i++) {
                int row = wm + i * 16 + (mat & 1) * 8 + wi;
                int col = k0 + (mat >> 1) * 8;
                LDMATRIX_X4(afr[i][0], afr[i][1], afr[i][2], afr[i][3],
                            aBase + row * APITCH_B + col * 2);
            }
#pragma unroll
            for (int jj = 0; jj < 2; jj++) {
                int n = wn + jj * 16 + (mat >> 1) * 8 + wi;
                int k = k0 + (mat & 1) * 8;
                LDMATRIX_X4(bfr[2 * jj][0], bfr[2 * jj][1],
                            bfr[2 * jj + 1][0], bfr[2 * jj + 1][1],
                            bBase + n * APITCH_B + k * 2);
            }
#pragma unroll
            for (int i = 0; i < 4; i++)
#pragma unroll
                for (int j = 0; j < 4; j++)
                    MMA_F16(acc[i][j], afr[i], bfr[j]);
        }
    }

    const int g = lid >> 2;
    const int tq = lid & 3;
#pragma unroll
    for (int i = 0; i < 4; i++) {
#pragma unroll
        for (int j = 0; j < 4; j++) {
            int row0 = bm + wm + i * 16 + g;
            int col = bn + wn + j * 8 + tq * 2;
            float b0 = bias[col], b1 = bias[col + 1];
            float v00 = acc[i][j][0] + b0, v01 = acc[i][j][1] + b1;
            float v10 = acc[i][j][2] + b0, v11 = acc[i][j][3] + b1;
            if (mode == 0) {
                *(float2*)(C + (size_t)row0 * N + col) = make_float2(v00, v01);
                *(float2*)(C + (size_t)(row0 + 8) * N + col) = make_float2(v10, v11);
            } else if (!isKV) {   // Q: fold softmax scale (log2 domain), split
                v00 *= SOFTMAX_SCALE_LOG2; v01 *= SOFTMAX_SCALE_LOG2;
                v10 *= SOFTMAX_SCALE_LOG2; v11 *= SOFTMAX_SCALE_LOG2;
                uint32_t h, l;
                split2h(v00, v01, h, l);
                *(uint32_t*)&gQhi[(size_t)row0 * HID_C + col] = h;
                *(uint32_t*)&gQlo[(size_t)row0 * HID_C + col] = l;
                split2h(v10, v11, h, l);
                *(uint32_t*)&gQhi[(size_t)(row0 + 8) * HID_C + col] = h;
                *(uint32_t*)&gQlo[(size_t)(row0 + 8) * HID_C + col] = l;
            } else {
                if (bn == 0) {    // K: hi only
                    *(uint32_t*)&gKhi[(size_t)row0 * HEAD_D + col] =
                        pack2h(v00, v01);
                    *(uint32_t*)&gKhi[(size_t)(row0 + 8) * HEAD_D + col] =
                        pack2h(v10, v11);
                } else {          // V: transpose, hi only
                    int d0 = col - 128;
                    float vs[2][2] = {{v00, v01}, {v10, v11}};
#pragma unroll
                    for (int rr = 0; rr < 2; rr++)
#pragma unroll
                        for (int cc = 0; cc < 2; cc++)
                            gVthi[(size_t)(d0 + cc) * M_ROWS + row0 + rr * 8] =
                                __float2half_rn(vs[rr][cc]);
                }
            }
        }
    }
}

// ---------------------------------------------------------------------------
// Flash attention, tensor-core fp16; Q carries hi+lo, K/V/P hi only; causal.
// CTA: 128 q-rows x (head, batch); 8 warps (m16); KV tile FN=128.
// QK^T loads each K fragment once; PV single-pass (P rounded to fp16).
// ---------------------------------------------------------------------------
#define FM 128
#define FN 128
#define SMQ_HI 0
#define SMQ_LO 32768
#define SM_STG 65536
#define STGSZ 65536
#define SK_OFF 0
#define SV_OFF 32768
#define FA_SMEM (65536 + 2 * STGSZ)   /* 196608 */

__global__ __launch_bounds__(256, 1)
void flash_mma_kernel()
{
    extern __shared__ char sm[];
    const uint32_t sb = smem_to_u32(sm);
    const int tid = threadIdx.x;
    const int wid = tid >> 5;
    const int lid = tid & 31;
    const int qt = (int)gridDim.x - 1 - (int)blockIdx.x;  // heavy blocks first
    const int h = blockIdx.y;
    const int b = blockIdx.z;
    const int m0 = qt * FM;
    const int wm = wid * 16;
    const size_t bS = (size_t)b * S_LEN;
    const int g = lid >> 2, tq = lid & 3;
    const int ntiles = qt + 1;

    auto issueQ = [&]() {
#pragma unroll
        for (int j = 0; j < 16; j++) {
            int idx = tid + j * 256;
            int arr = idx >> 11;
            int rem = idx & 2047;
            int r = rem >> 4, c16 = rem & 15;
            const __half* src =
                (arr ? gQlo : gQhi) + (bS + m0 + r) * HID_C + h * HEAD_D + c16 * 8;
            CP_ASYNC16(sb + (arr ? SMQ_LO : SMQ_HI) + r * 256 + ((c16 ^ (r & 7)) << 4),
                       (const char*)src);
        }
    };
    auto issueKV = [&](int t, int s) {
        const uint32_t st = sb + SM_STG + s * STGSZ;
        const int n0 = t * FN;
#pragma unroll
        for (int j = 0; j < 8; j++) {
            int idx = tid + j * 256;
            int r = idx >> 4, c16 = idx & 15;
            const __half* src = gKhi + (bS + n0 + r) * HEAD_D + c16 * 8;
            CP_ASYNC16(st + SK_OFF + r * 256 + ((c16 ^ (r & 7)) << 4),
                       (const char*)src);
        }
#pragma unroll
        for (int j = 0; j < 8; j++) {
            int idx = tid + j * 256;
            int r = idx >> 4, c16 = idx & 15;
            const __half* src = gVthi + (size_t)r * M_ROWS + bS + n0 + c16 * 8;
            CP_ASYNC16(st + SV_OFF + r * 256 + ((c16 ^ (r & 7)) << 4),
                       (const char*)src);
        }
    };

    issueQ();
    issueKV(0, 0);
    CP_COMMIT();
    if (ntiles > 1) issueKV(1, 1);
    CP_COMMIT();
    CP_WAIT1();
    __syncthreads();

    float oacc[16][4];
#pragma unroll
    for (int i = 0; i < 16; i++)
#pragma unroll
        for (int q = 0; q < 4; q++) oacc[i][q] = 0.f;
    float mst[2] = {-1e30f, -1e30f};
    float lst[2] = {0.f, 0.f};

    const int mat = lid >> 3;
    const int wi = lid & 7;

    for (int t = 0; t < ntiles; t++) {
        const uint32_t st = sb + SM_STG + (t & 1) * STGSZ;

        // ---- S = (Qh + Ql) K^T : K fragments loaded once ----
        float sacc[16][4];
#pragma unroll
        for (int i = 0; i < 16; i++)
#pragma unroll
            for (int q = 0; q < 4; q++) sacc[i][q] = 0.f;

        {
            const uint32_t kb = st + SK_OFF;
#pragma unroll
            for (int kk = 0; kk < 8; kk++) {
                uint32_t ah[4], alq[4];
                {
                    int r = wm + (lid & 15);
                    int c16 = 2 * kk + (lid >> 4);
                    uint32_t off = r * 256 + ((c16 ^ (r & 7)) << 4);
                    LDMATRIX_X4(ah[0], ah[1], ah[2], ah[3], sb + SMQ_HI + off);
                    LDMATRIX_X4(alq[0], alq[1], alq[2], alq[3], sb + SMQ_LO + off);
                }
#pragma unroll
                for (int jj = 0; jj < 8; jj++) {
                    int r = jj * 16 + (mat >> 1) * 8 + wi;
                    int c16 = 2 * kk + (mat & 1);
                    uint32_t v[4];
                    LDMATRIX_X4(v[0], v[1], v[2], v[3],
                                kb + r * 256 + ((c16 ^ (r & 7)) << 4));
                    MMA_F16(sacc[2 * jj], ah, v);
                    MMA_F16(sacc[2 * jj], alq, v);
                    MMA_F16(sacc[2 * jj + 1], ah, (v + 2));
                    MMA_F16(sacc[2 * jj + 1], alq, (v + 2));
                }
            }
        }

        // ---- causal mask (diagonal tile only) ----
        if (t == qt) {
#pragma unroll
            for (int nb = 0; nb < 16; nb++)
#pragma unroll
                for (int q = 0; q < 4; q++) {
                    int col = t * FN + nb * 8 + tq * 2 + (q & 1);
                    int row = m0 + wm + g + (q >> 1) * 8;
                    if (col > row) sacc[nb][q] = -1e30f;
                }
        }

        // ---- online softmax (log2 domain) ----
#pragma unroll
        for (int hf = 0; hf < 2; hf++) {
            float tm = -1e30f;
#pragma unroll
            for (int nb = 0; nb < 16; nb++) {
                tm = fmaxf(tm, fmaxf(sacc[nb][2 * hf], sacc[nb][2 * hf + 1]));
            }
            tm = fmaxf(tm, __shfl_xor_sync(0xffffffffu, tm, 1));
            tm = fmaxf(tm, __shfl_xor_sync(0xffffffffu, tm, 2));
            float mn = fmaxf(mst[hf], tm);
            float corr = exp2f(mst[hf] - mn);
            mst[hf] = mn;
            float sum = 0.f;
#pragma unroll
            for (int nb = 0; nb < 16; nb++) {
#pragma unroll
                for (int e = 0; e < 2; e++) {
                    float p = exp2f(sacc[nb][2 * hf + e] - mn);
                    sacc[nb][2 * hf + e] = p;
                    sum += p;
                }
            }
            sum += __shfl_xor_sync(0xffffffffu, sum, 1);
            sum += __shfl_xor_sync(0xffffffffu, sum, 2);
            lst[hf] = lst[hf] * corr + sum;
#pragma unroll
            for (int nb = 0; nb < 16; nb++) {
                oacc[nb][2 * hf + 0] *= corr;
                oacc[nb][2 * hf + 1] *= corr;
            }
        }

        // ---- O += Ph Vh (single-pass PV; P rounded to fp16) ----
#pragma unroll
        for (int kk = 0; kk < 8; kk++) {
            uint32_t ah[4];
            ah[0] = pack2h(sacc[2 * kk][0], sacc[2 * kk][1]);
            ah[1] = pack2h(sacc[2 * kk][2], sacc[2 * kk][3]);
            ah[2] = pack2h(sacc[2 * kk + 1][0], sacc[2 * kk + 1][1]);
            ah[3] = pack2h(sacc[2 * kk + 1][2], sacc[2 * kk + 1][3]);
#pragma unroll
            for (int jj = 0; jj < 8; jj++) {
                int r = jj * 16 + (mat >> 1) * 8 + wi;
                int c16 = 2 * kk + (mat & 1);
                uint32_t v[4];
                LDMATRIX_X4(v[0], v[1], v[2], v[3],
                            st + SV_OFF + r * 256 + ((c16 ^ (r & 7)) << 4));
                MMA_F16(oacc[2 * jj], ah, v);
                MMA_F16(oacc[2 * jj + 1], ah, (v + 2));
            }
        }

        __syncthreads();
        if (t + 2 < ntiles) issueKV(t + 2, t & 1);
        CP_COMMIT();
        if (t + 1 < ntiles) {
            CP_WAIT1();
        } else {
            CP_WAIT0();
        }
        __syncthreads();
    }

    // ---- epilogue: O/l -> fp16 into gA_hi ----
#pragma unroll
    for (int hf = 0; hf < 2; hf++) {
        float inv = 1.f / lst[hf];
        size_t row = bS + m0 + wm + g + hf * 8;
#pragma unroll
        for (int nb = 0; nb < 16; nb++) {
            float v0 = oacc[nb][2 * hf] * inv;
            float v1 = oacc[nb][2 * hf + 1] * inv;
            size_t off = row * HID_C + h * HEAD_D + nb * 8 + tq * 2;
            *(uint32_t*)&gA_hi[off] = pack2h(v0, v1);
        }
    }
}

// ---------------------------------------------------------------------------
extern "C" void kernel_launch(void* const* d_in, const int* in_sizes, int n_in,
                              void* d_out, int out_size)
{
    (void)in_sizes; (void)n_in; (void)out_size;
    const float* hs  = (const float*)d_in[0];
    /* d_in[1] = attention_mask (exact causal tril) applied analytically */
    const float* Wq  = (const float*)d_in[2];
    const float* bq  = (const float*)d_in[3];
    const float* Wkv = (const float*)d_in[4];
    const float* bkv = (const float*)d_in[5];
    const float* Wp  = (const float*)d_in[6];
    const float* bp  = (const float*)d_in[7];
    float* out = (float*)d_out;

    __half *pAhi, *pWqh, *pWkh, *pWph;
    cudaGetSymbolAddress((void**)&pAhi, gA_hi);
    cudaGetSymbolAddress((void**)&pWqh, gWq_hi);
    cudaGetSymbolAddress((void**)&pWkh, gWkv_hi);
    cudaGetSymbolAddress((void**)&pWph, gWp_hi);

    cudaFuncSetAttribute(mma_gemm_kernel,
                         cudaFuncAttributeMaxDynamicSharedMemorySize, GEMM_SMEM);
    cudaFuncSetAttribute(flash_mma_kernel,
                         cudaFuncAttributeMaxDynamicSharedMemorySize, FA_SMEM);

    // 1. convert hidden states to fp16
    {
        int n4 = M_ROWS * HID_C / 4;
        conv_f32_kernel<<<(n4 + 255) / 256, 256>>>(hs, pAhi, n4);
    }
    // 2. fused transpose+convert of all three weights
    tconv_all_kernel<<<dim3(HID_C / 32, HID_C / 32, 3), dim3(32, 8)>>>(Wq, Wp, Wkv);

    // 3. fused Q + KV projection (single-product; Q split from fp32 accum)
    mma_gemm_kernel<<<dim3(18, M_ROWS / BM), 256, GEMM_SMEM>>>(
        pAhi, pWqh, bq, pWkh, bkv, nullptr, HID_C, 1);
    // 4. attention -> gA_hi (fp16)
    flash_mma_kernel<<<dim3(S_LEN / FM, N_HEADS, B_SZ), 256, FA_SMEM>>>();
    // 5. out = attn @ Wp + bp (single-product)
    mma_gemm_kernel<<<dim3(16, M_ROWS / BM), 256, GEMM_SMEM>>>(
        pAhi, pWph, bp, nullptr, nullptr, out, HID_C, 0);
}

// round 15
// speedup vs baseline: 2.5448x; 1.1029x over previous
#include <cuda_runtime.h>
#include <cuda_fp16.h>
#include <cstdint>

#define B_SZ 2
#define S_LEN 2048
#define HID_C 2048
#define N_HEADS 16
#define HEAD_D 128
#define M_ROWS (B_SZ * S_LEN)   /* 4096 */
#define KV_C 256

#define SOFTMAX_SCALE_LOG2 0.12754404735576283f       /* 1/sqrt(128)*log2(e) */

// ---------------------------------------------------------------------------
// Device-global scratch (allocation-free rule)
// ---------------------------------------------------------------------------
__device__ __half gA_hi[(size_t)M_ROWS * HID_C];   // hs / attn (fp16, left operand)
__device__ __half gQhi[(size_t)M_ROWS * HID_C];    // pre-scaled by 1/sqrt(d)*log2e
__device__ __half gKhi[(size_t)M_ROWS * HEAD_D];          // right operand: hi only
__device__ __half gVthi[(size_t)HEAD_D * M_ROWS];         // V^T [d][bS], hi only
__device__ __half gWq_hi[(size_t)HID_C * HID_C];
__device__ __half gWkv_hi[(size_t)KV_C * HID_C];
__device__ __half gWp_hi[(size_t)HID_C * HID_C];

__device__ __forceinline__ uint32_t smem_to_u32(const void* p) {
    uint32_t a;
    asm("{ .reg .u64 t; cvta.to.shared.u64 t, %1; cvt.u32.u64 %0, t; }"
        : "=r"(a) : "l"(p));
    return a;
}

#define CP_ASYNC16(sm, g) \
    asm volatile("cp.async.cg.shared.global [%0], [%1], 16;" \
                 :: "r"(sm), "l"(g) : "memory")
#define CP_COMMIT() asm volatile("cp.async.commit_group;" ::: "memory")
#define CP_WAIT1()  asm volatile("cp.async.wait_group 1;" ::: "memory")
#define CP_WAIT0()  asm volatile("cp.async.wait_group 0;" ::: "memory")

#define LDMATRIX_X4(r0, r1, r2, r3, addr) \
    asm volatile("ldmatrix.sync.aligned.m8n8.x4.shared.b16 {%0,%1,%2,%3}, [%4];" \
                 : "=r"(r0), "=r"(r1), "=r"(r2), "=r"(r3) : "r"(addr))

#define MMA_F16(d, a, b) \
    asm volatile("mma.sync.aligned.m16n8k16.row.col.f32.f16.f16.f32 " \
                 "{%0,%1,%2,%3}, {%4,%5,%6,%7}, {%8,%9}, {%0,%1,%2,%3};" \
                 : "+f"((d)[0]), "+f"((d)[1]), "+f"((d)[2]), "+f"((d)[3]) \
                 : "r"((a)[0]), "r"((a)[1]), "r"((a)[2]), "r"((a)[3]), \
                   "r"((b)[0]), "r"((b)[1]))

__device__ __forceinline__ uint32_t pack2h(float v0, float v1) {
    __half2 t = __floats2half2_rn(v0, v1);
    return *reinterpret_cast<uint32_t*>(&t);
}

// ---------------------------------------------------------------------------
// fp32 -> fp16 convert (hs consumed in fp16)
// ---------------------------------------------------------------------------
__global__ void conv_f32_kernel(const float* __restrict__ src,
                                __half* __restrict__ hi, int n4)
{
    int i = blockIdx.x * blockDim.x + threadIdx.x;
    if (i >= n4) return;
    float4 v = ((const float4*)src)[i];
    ((uint32_t*)hi)[2 * i] = pack2h(v.x, v.y);
    ((uint32_t*)hi)[2 * i + 1] = pack2h(v.z, v.w);
}

// ---------------------------------------------------------------------------
// Fused weight transpose+convert: z=0 Wq, z=1 Wp, z=2 Wkv
// ---------------------------------------------------------------------------
__global__ void tconv_all_kernel(const float* __restrict__ Wq,
                                 const float* __restrict__ Wp,
                                 const float* __restrict__ Wkv)
{
    const int z = blockIdx.z;
    const float* W = (z == 0) ? Wq : (z == 1) ? Wp : Wkv;
    __half* T = (z == 0) ? gWq_hi : (z == 1) ? gWp_hi : gWkv_hi;
    const int N = (z == 2) ? KV_C : HID_C;
    if (blockIdx.x * 32 >= N) return;

    __shared__ float tile[32][33];
    int n0 = blockIdx.x * 32, k0 = blockIdx.y * 32;
    int tx = threadIdx.x, ty = threadIdx.y;
#pragma unroll
    for (int j = 0; j < 32; j += 8)
        tile[ty + j][tx] = W[(size_t)(k0 + ty + j) * N + n0 + tx];
    __syncthreads();
#pragma unroll
    for (int j = 0; j < 32; j += 8)
        T[(size_t)(n0 + ty + j) * HID_C + k0 + tx] =
            __float2half_rn(tile[tx][ty + j]);
}

// ---------------------------------------------------------------------------
// mma.sync fp16 GEMM: C = Ah @ Bh^T + bias  (single product, 32 chunks)
// K-chunk = 64 halves (128B/row, pitch 144 -> conflict-free ldmatrix)
// 256 threads, 8 warps (2x4), warp tile 64x32, 3-stage cp.async, 2 CTA/SM.
// mode 0: out-proj -> fp32 C (B0 = Wp)
// mode 1: fused QKV: bx<16 -> Q (B0=Wq) scaled -> gQhi (fp16)
//                    bx>=16 -> KV (B1=Wkv): bn==0 -> K hi; bn==128 -> V^T hi
// ---------------------------------------------------------------------------
#define BM 128
#define BN 128
#define BKH 64                  /* halves per chunk */
#define APITCH_B 144            /* 128B data + 16B pad */
#define STG_A (BM * APITCH_B)   /* 18432 */
#define STG_B (BN * APITCH_B)
#define STG_BYTES (STG_A + STG_B)  /* 36864 */
#define NSTAGE 3
#define GEMM_SMEM (NSTAGE * STG_BYTES)  /* 110592 */
#define NCHUNK 32               /* single emulation phase */

__global__ __launch_bounds__(256, 2)
void mma_gemm_kernel(const __half* __restrict__ Ahi,
                     const __half* __restrict__ B0,
                     const float* __restrict__ bias0,
                     const __half* __restrict__ B1,
                     const float* __restrict__ bias1,
                     float* __restrict__ C, int N, int mode)
{
    extern __shared__ char smem[];
    const uint32_t smem_base = smem_to_u32(smem);
    const int tid = threadIdx.x;
    const int wid = tid >> 5;
    const int lid = tid & 31;
    const int bm = blockIdx.y * BM;
    const bool isKV = (mode == 1) && (blockIdx.x >= 16);
    const int bn = isKV ? (blockIdx.x - 16) * BN : blockIdx.x * BN;
    const __half* Bh = isKV ? B1 : B0;
    const float* bias = isKV ? bias1 : bias0;

    auto issue = [&](int c, int stage) {
        const size_t k0 = (size_t)c * BKH;
        const uint32_t sA = smem_base + stage * STG_BYTES;
        const uint32_t sB = sA + STG_A;
#pragma unroll
        for (int j = 0; j < 4; j++) {
            int seg = tid + j * 256;
            int r = seg >> 3, s = seg & 7;
            CP_ASYNC16(sA + r * APITCH_B + s * 16,
                       (const char*)(Ahi + (size_t)(bm + r) * HID_C + k0 + s * 8));
        }
#pragma unroll
        for (int j = 0; j < 4; j++) {
            int seg = tid + j * 256;
            int r = seg >> 3, s = seg & 7;
            CP_ASYNC16(sB + r * APITCH_B + s * 16,
                       (const char*)(Bh + (size_t)(bn + r) * HID_C + k0 + s * 8));
        }
    };

    float acc[4][4][4];
#pragma unroll
    for (int i = 0; i < 4; i++)
#pragma unroll
        for (int j = 0; j < 4; j++)
#pragma unroll
            for (int q = 0; q < 4; q++) acc[i][j][q] = 0.f;

    issue(0, 0); CP_COMMIT();
    issue(1, 1); CP_COMMIT();

    const int wm = (wid >> 2) * 64;
    const int wn = (wid & 3) * 32;
    const int mat = lid >> 3;
    const int wi = lid & 7;

    for (int t = 0; t < NCHUNK; t++) {
        CP_WAIT1();
        __syncthreads();
        if (t + 2 < NCHUNK) issue(t + 2, (t + 2) % NSTAGE);
        CP_COMMIT();

        const uint32_t aBase = smem_base + (t % NSTAGE) * STG_BYTES;
        const uint32_t bBase = aBase + STG_A;
#pragma unroll
        for (int ks = 0; ks < 4; ks++) {
            const int k0 = ks * 16;
            uint32_t afr[4][4];
            uint32_t bfr[4][2];
#pragma unroll
            for (int i = 0; i < 4; i++) {
                int row = wm + i * 16 + (mat & 1) * 8 + wi;
                int col = k0 + (mat >> 1) * 8;
                LDMATRIX_X4(afr[i][0], afr[i][1], afr[i][2], afr[i][3],
                            aBase + row * APITCH_B + col * 2);
            }
#pragma unroll
            for (int jj = 0; jj < 2; jj++) {
                int n = wn + jj * 16 + (mat >> 1) * 8 + wi;
                int k = k0 + (mat & 1) * 8;
                LDMATRIX_X4(bfr[2 * jj][0], bfr[2 * jj][1],
                            bfr[2 * jj + 1][0], bfr[2 * jj + 1][1],
                            bBase + n * APITCH_B + k * 2);
            }
#pragma unroll
            for (int i = 0; i < 4; i++)
#pragma unroll
                for (int j = 0; j < 4; j++)
                    MMA_F16(acc[i][j], afr[i], bfr[j]);
        }
    }

    const int g = lid >> 2;
    const int tq = lid & 3;
#pragma unroll
    for (int i = 0; i < 4; i++) {
#pragma unroll
        for (int j = 0; j < 4; j++) {
            int row0 = bm + wm + i * 16 + g;
            int col = bn + wn + j * 8 + tq * 2;
            float b0 = bias[col], b1 = bias[col + 1];
            float v00 = acc[i][j][0] + b0, v01 = acc[i][j][1] + b1;
            float v10 = acc[i][j][2] + b0, v11 = acc[i][j][3] + b1;
            if (mode == 0) {
                *(float2*)(C + (size_t)row0 * N + col) = make_float2(v00, v01);
                *(float2*)(C + (size_t)(row0 + 8) * N + col) = make_float2(v10, v11);
            } else if (!isKV) {   // Q: fold softmax scale (log2 domain), fp16
                v00 *= SOFTMAX_SCALE_LOG2; v01 *= SOFTMAX_SCALE_LOG2;
                v10 *= SOFTMAX_SCALE_LOG2; v11 *= SOFTMAX_SCALE_LOG2;
                *(uint32_t*)&gQhi[(size_t)row0 * HID_C + col] = pack2h(v00, v01);
                *(uint32_t*)&gQhi[(size_t)(row0 + 8) * HID_C + col] = pack2h(v10, v11);
            } else {
                if (bn == 0) {    // K: hi only
                    *(uint32_t*)&gKhi[(size_t)row0 * HEAD_D + col] =
                        pack2h(v00, v01);
                    *(uint32_t*)&gKhi[(size_t)(row0 + 8) * HEAD_D + col] =
                        pack2h(v10, v11);
                } else {          // V: transpose, hi only
                    int d0 = col - 128;
                    float vs[2][2] = {{v00, v01}, {v10, v11}};
#pragma unroll
                    for (int rr = 0; rr < 2; rr++)
#pragma unroll
                        for (int cc = 0; cc < 2; cc++)
                            gVthi[(size_t)(d0 + cc) * M_ROWS + row0 + rr * 8] =
                                __float2half_rn(vs[rr][cc]);
                }
            }
        }
    }
}

// ---------------------------------------------------------------------------
// Flash attention, tensor-core fp16; Q/K/V/P all fp16 (single QK pass); causal.
// CTA: 128 q-rows x (head, batch); 8 warps (m16); KV tile FN=128.
// Smem: Q [128][128]h (32KB) + 2 stages {K [128][128]h, Vt [128][128]h}
// ---------------------------------------------------------------------------
#define FM 128
#define FN 128
#define SMQ_HI 0
#define SM_STG 32768
#define STGSZ 65536
#define SK_OFF 0
#define SV_OFF 32768
#define FA_SMEM (32768 + 2 * STGSZ)   /* 163840 */

__global__ __launch_bounds__(256, 1)
void flash_mma_kernel()
{
    extern __shared__ char sm[];
    const uint32_t sb = smem_to_u32(sm);
    const int tid = threadIdx.x;
    const int wid = tid >> 5;
    const int lid = tid & 31;
    const int qt = (int)gridDim.x - 1 - (int)blockIdx.x;  // heavy blocks first
    const int h = blockIdx.y;
    const int b = blockIdx.z;
    const int m0 = qt * FM;
    const int wm = wid * 16;
    const size_t bS = (size_t)b * S_LEN;
    const int g = lid >> 2, tq = lid & 3;
    const int ntiles = qt + 1;

    auto issueQ = [&]() {
#pragma unroll
        for (int j = 0; j < 8; j++) {
            int idx = tid + j * 256;
            int r = idx >> 4, c16 = idx & 15;
            const __half* src =
                gQhi + (bS + m0 + r) * HID_C + h * HEAD_D + c16 * 8;
            CP_ASYNC16(sb + SMQ_HI + r * 256 + ((c16 ^ (r & 7)) << 4),
                       (const char*)src);
        }
    };
    auto issueKV = [&](int t, int s) {
        const uint32_t st = sb + SM_STG + s * STGSZ;
        const int n0 = t * FN;
#pragma unroll
        for (int j = 0; j < 8; j++) {
            int idx = tid + j * 256;
            int r = idx >> 4, c16 = idx & 15;
            const __half* src = gKhi + (bS + n0 + r) * HEAD_D + c16 * 8;
            CP_ASYNC16(st + SK_OFF + r * 256 + ((c16 ^ (r & 7)) << 4),
                       (const char*)src);
        }
#pragma unroll
        for (int j = 0; j < 8; j++) {
            int idx = tid + j * 256;
            int r = idx >> 4, c16 = idx & 15;
            const __half* src = gVthi + (size_t)r * M_ROWS + bS + n0 + c16 * 8;
            CP_ASYNC16(st + SV_OFF + r * 256 + ((c16 ^ (r & 7)) << 4),
                       (const char*)src);
        }
    };

    issueQ();
    issueKV(0, 0);
    CP_COMMIT();
    if (ntiles > 1) issueKV(1, 1);
    CP_COMMIT();
    CP_WAIT1();
    __syncthreads();

    float oacc[16][4];
#pragma unroll
    for (int i = 0; i < 16; i++)
#pragma unroll
        for (int q = 0; q < 4; q++) oacc[i][q] = 0.f;
    float mst[2] = {-1e30f, -1e30f};
    float lst[2] = {0.f, 0.f};

    const int mat = lid >> 3;
    const int wi = lid & 7;

    for (int t = 0; t < ntiles; t++) {
        const uint32_t st = sb + SM_STG + (t & 1) * STGSZ;

        // ---- S = Q K^T : single pass (Q fp16) ----
        float sacc[16][4];
#pragma unroll
        for (int i = 0; i < 16; i++)
#pragma unroll
            for (int q = 0; q < 4; q++) sacc[i][q] = 0.f;

        {
            const uint32_t kb = st + SK_OFF;
#pragma unroll
            for (int kk = 0; kk < 8; kk++) {
                uint32_t ah[4];
                {
                    int r = wm + (lid & 15);
                    int c16 = 2 * kk + (lid >> 4);
                    uint32_t off = r * 256 + ((c16 ^ (r & 7)) << 4);
                    LDMATRIX_X4(ah[0], ah[1], ah[2], ah[3], sb + SMQ_HI + off);
                }
#pragma unroll
                for (int jj = 0; jj < 8; jj++) {
                    int r = jj * 16 + (mat >> 1) * 8 + wi;
                    int c16 = 2 * kk + (mat & 1);
                    uint32_t v[4];
                    LDMATRIX_X4(v[0], v[1], v[2], v[3],
                                kb + r * 256 + ((c16 ^ (r & 7)) << 4));
                    MMA_F16(sacc[2 * jj], ah, v);
                    MMA_F16(sacc[2 * jj + 1], ah, (v + 2));
                }
            }
        }

        // ---- causal mask (diagonal tile only) ----
        if (t == qt) {
#pragma unroll
            for (int nb = 0; nb < 16; nb++)
#pragma unroll
                for (int q = 0; q < 4; q++) {
                    int col = t * FN + nb * 8 + tq * 2 + (q & 1);
                    int row = m0 + wm + g + (q >> 1) * 8;
                    if (col > row) sacc[nb][q] = -1e30f;
                }
        }

        // ---- online softmax (log2 domain) ----
#pragma unroll
        for (int hf = 0; hf < 2; hf++) {
            float tm = -1e30f;
#pragma unroll
            for (int nb = 0; nb < 16; nb++) {
                tm = fmaxf(tm, fmaxf(sacc[nb][2 * hf], sacc[nb][2 * hf + 1]));
            }
            tm = fmaxf(tm, __shfl_xor_sync(0xffffffffu, tm, 1));
            tm = fmaxf(tm, __shfl_xor_sync(0xffffffffu, tm, 2));
            float mn = fmaxf(mst[hf], tm);
            float corr = exp2f(mst[hf] - mn);
            mst[hf] = mn;
            float sum = 0.f;
#pragma unroll
            for (int nb = 0; nb < 16; nb++) {
#pragma unroll
                for (int e = 0; e < 2; e++) {
                    float p = exp2f(sacc[nb][2 * hf + e] - mn);
                    sacc[nb][2 * hf + e] = p;
                    sum += p;
                }
            }
            sum += __shfl_xor_sync(0xffffffffu, sum, 1);
            sum += __shfl_xor_sync(0xffffffffu, sum, 2);
            lst[hf] = lst[hf] * corr + sum;
#pragma unroll
            for (int nb = 0; nb < 16; nb++) {
                oacc[nb][2 * hf + 0] *= corr;
                oacc[nb][2 * hf + 1] *= corr;
            }
        }

        // ---- O += Ph Vh (single-pass PV; P rounded to fp16) ----
#pragma unroll
        for (int kk = 0; kk < 8; kk++) {
            uint32_t ah[4];
            ah[0] = pack2h(sacc[2 * kk][0], sacc[2 * kk][1]);
            ah[1] = pack2h(sacc[2 * kk][2], sacc[2 * kk][3]);
            ah[2] = pack2h(sacc[2 * kk + 1][0], sacc[2 * kk + 1][1]);
            ah[3] = pack2h(sacc[2 * kk + 1][2], sacc[2 * kk + 1][3]);
#pragma unroll
            for (int jj = 0; jj < 8; jj++) {
                int r = jj * 16 + (mat >> 1) * 8 + wi;
                int c16 = 2 * kk + (mat & 1);
                uint32_t v[4];
                LDMATRIX_X4(v[0], v[1], v[2], v[3],
                            st + SV_OFF + r * 256 + ((c16 ^ (r & 7)) << 4));
                MMA_F16(oacc[2 * jj], ah, v);
                MMA_F16(oacc[2 * jj + 1], ah, (v + 2));
            }
        }

        __syncthreads();
        if (t + 2 < ntiles) issueKV(t + 2, t & 1);
        CP_COMMIT();
        if (t + 1 < ntiles) {
            CP_WAIT1();
        } else {
            CP_WAIT0();
        }
        __syncthreads();
    }

    // ---- epilogue: O/l -> fp16 into gA_hi ----
#pragma unroll
    for (int hf = 0; hf < 2; hf++) {
        float inv = 1.f / lst[hf];
        size_t row = bS + m0 + wm + g + hf * 8;
#pragma unroll
        for (int nb = 0; nb < 16; nb++) {
            float v0 = oacc[nb][2 * hf] * inv;
            float v1 = oacc[nb][2 * hf + 1] * inv;
            size_t off = row * HID_C + h * HEAD_D + nb * 8 + tq * 2;
            *(uint32_t*)&gA_hi[off] = pack2h(v0, v1);
        }
    }
}

// ---------------------------------------------------------------------------
extern "C" void kernel_launch(void* const* d_in, const int* in_sizes, int n_in,
                              void* d_out, int out_size)
{
    (void)in_sizes; (void)n_in; (void)out_size;
    const float* hs  = (const float*)d_in[0];
    /* d_in[1] = attention_mask (exact causal tril) applied analytically */
    const float* Wq  = (const float*)d_in[2];
    const float* bq  = (const float*)d_in[3];
    const float* Wkv = (const float*)d_in[4];
    const float* bkv = (const float*)d_in[5];
    const float* Wp  = (const float*)d_in[6];
    const float* bp  = (const float*)d_in[7];
    float* out = (float*)d_out;

    __half *pAhi, *pWqh, *pWkh, *pWph;
    cudaGetSymbolAddress((void**)&pAhi, gA_hi);
    cudaGetSymbolAddress((void**)&pWqh, gWq_hi);
    cudaGetSymbolAddress((void**)&pWkh, gWkv_hi);
    cudaGetSymbolAddress((void**)&pWph, gWp_hi);

    cudaFuncSetAttribute(mma_gemm_kernel,
                         cudaFuncAttributeMaxDynamicSharedMemorySize, GEMM_SMEM);
    cudaFuncSetAttribute(flash_mma_kernel,
                         cudaFuncAttributeMaxDynamicSharedMemorySize, FA_SMEM);

    // 1. convert hidden states to fp16
    {
        int n4 = M_ROWS * HID_C / 4;
        conv_f32_kernel<<<(n4 + 255) / 256, 256>>>(hs, pAhi, n4);
    }
    // 2. fused transpose+convert of all three weights
    tconv_all_kernel<<<dim3(HID_C / 32, HID_C / 32, 3), dim3(32, 8)>>>(Wq, Wp, Wkv);

    // 3. fused Q + KV projection (single-product)
    mma_gemm_kernel<<<dim3(18, M_ROWS / BM), 256, GEMM_SMEM>>>(
        pAhi, pWqh, bq, pWkh, bkv, nullptr, HID_C, 1);
    // 4. attention -> gA_hi (fp16)
    flash_mma_kernel<<<dim3(S_LEN / FM, N_HEADS, B_SZ), 256, FA_SMEM>>>();
    // 5. out = attn @ Wp + bp (single-product)
    mma_gemm_kernel<<<dim3(16, M_ROWS / BM), 256, GEMM_SMEM>>>(
        pAhi, pWph, bp, nullptr, nullptr, out, HID_C, 0);
}

// round 16
// speedup vs baseline: 2.5471x; 1.0009x over previous
#include <cuda_runtime.h>
#include <cuda_fp16.h>
#include <cstdint>

#define B_SZ 2
#define S_LEN 2048
#define HID_C 2048
#define N_HEADS 16
#define HEAD_D 128
#define M_ROWS (B_SZ * S_LEN)   /* 4096 */
#define KV_C 256

#define SOFTMAX_SCALE_LOG2 0.12754404735576283f       /* 1/sqrt(128)*log2(e) */

// ---------------------------------------------------------------------------
// Device-global scratch (allocation-free rule)
// ---------------------------------------------------------------------------
__device__ __half gA_hi[(size_t)M_ROWS * HID_C];   // hs / attn (fp16, left operand)
__device__ __half gQhi[(size_t)M_ROWS * HID_C];    // pre-scaled by 1/sqrt(d)*log2e
__device__ __half gKhi[(size_t)M_ROWS * HEAD_D];          // right operand: hi only
__device__ __half gVthi[(size_t)HEAD_D * M_ROWS];         // V^T [d][bS], hi only
__device__ __half gWq_hi[(size_t)HID_C * HID_C];
__device__ __half gWkv_hi[(size_t)KV_C * HID_C];
__device__ __half gWp_hi[(size_t)HID_C * HID_C];

__device__ __forceinline__ uint32_t smem_to_u32(const void* p) {
    uint32_t a;
    asm("{ .reg .u64 t; cvta.to.shared.u64 t, %1; cvt.u32.u64 %0, t; }"
        : "=r"(a) : "l"(p));
    return a;
}

#define CP_ASYNC16(sm, g) \
    asm volatile("cp.async.cg.shared.global [%0], [%1], 16;" \
                 :: "r"(sm), "l"(g) : "memory")
#define CP_COMMIT() asm volatile("cp.async.commit_group;" ::: "memory")
#define CP_WAIT1()  asm volatile("cp.async.wait_group 1;" ::: "memory")
#define CP_WAIT0()  asm volatile("cp.async.wait_group 0;" ::: "memory")

#define LDMATRIX_X4(r0, r1, r2, r3, addr) \
    asm volatile("ldmatrix.sync.aligned.m8n8.x4.shared.b16 {%0,%1,%2,%3}, [%4];" \
                 : "=r"(r0), "=r"(r1), "=r"(r2), "=r"(r3) : "r"(addr))

#define MMA_F16(d, a, b) \
    asm volatile("mma.sync.aligned.m16n8k16.row.col.f32.f16.f16.f32 " \
                 "{%0,%1,%2,%3}, {%4,%5,%6,%7}, {%8,%9}, {%0,%1,%2,%3};" \
                 : "+f"((d)[0]), "+f"((d)[1]), "+f"((d)[2]), "+f"((d)[3]) \
                 : "r"((a)[0]), "r"((a)[1]), "r"((a)[2]), "r"((a)[3]), \
                   "r"((b)[0]), "r"((b)[1]))

__device__ __forceinline__ uint32_t pack2h(float v0, float v1) {
    __half2 t = __floats2half2_rn(v0, v1);
    return *reinterpret_cast<uint32_t*>(&t);
}

// ---------------------------------------------------------------------------
// fp32 -> fp16 convert (hs consumed in fp16)
// ---------------------------------------------------------------------------
__global__ void conv_f32_kernel(const float* __restrict__ src,
                                __half* __restrict__ hi, int n4)
{
    int i = blockIdx.x * blockDim.x + threadIdx.x;
    if (i >= n4) return;
    float4 v = ((const float4*)src)[i];
    ((uint32_t*)hi)[2 * i] = pack2h(v.x, v.y);
    ((uint32_t*)hi)[2 * i + 1] = pack2h(v.z, v.w);
}

// ---------------------------------------------------------------------------
// Fused weight transpose+convert: z=0 Wq, z=1 Wp, z=2 Wkv
// ---------------------------------------------------------------------------
__global__ void tconv_all_kernel(const float* __restrict__ Wq,
                                 const float* __restrict__ Wp,
                                 const float* __restrict__ Wkv)
{
    const int z = blockIdx.z;
    const float* W = (z == 0) ? Wq : (z == 1) ? Wp : Wkv;
    __half* T = (z == 0) ? gWq_hi : (z == 1) ? gWp_hi : gWkv_hi;
    const int N = (z == 2) ? KV_C : HID_C;
    if (blockIdx.x * 32 >= N) return;

    __shared__ float tile[32][33];
    int n0 = blockIdx.x * 32, k0 = blockIdx.y * 32;
    int tx = threadIdx.x, ty = threadIdx.y;
#pragma unroll
    for (int j = 0; j < 32; j += 8)
        tile[ty + j][tx] = W[(size_t)(k0 + ty + j) * N + n0 + tx];
    __syncthreads();
#pragma unroll
    for (int j = 0; j < 32; j += 8)
        T[(size_t)(n0 + ty + j) * HID_C + k0 + tx] =
            __float2half_rn(tile[tx][ty + j]);
}

// ---------------------------------------------------------------------------
// mma.sync fp16 GEMM: C = Ah @ Bh^T + bias  (single product, 32 chunks)
// K-chunk = 64 halves (128B/row, pitch 144 -> conflict-free ldmatrix)
// 256 threads, 8 warps (2x4), warp tile 64x32, 3-stage cp.async, 2 CTA/SM.
// mode 0: out-proj -> fp32 C (B0 = Wp)
// mode 1: fused QKV: bx<16 -> Q (B0=Wq) scaled -> gQhi (fp16)
//                    bx>=16 -> KV (B1=Wkv): bn==0 -> K hi; bn==128 -> V^T hi
// ---------------------------------------------------------------------------
#define BM 128
#define BN 128
#define BKH 64                  /* halves per chunk */
#define APITCH_B 144            /* 128B data + 16B pad */
#define STG_A (BM * APITCH_B)   /* 18432 */
#define STG_B (BN * APITCH_B)
#define STG_BYTES (STG_A + STG_B)  /* 36864 */
#define NSTAGE 3
#define GEMM_SMEM (NSTAGE * STG_BYTES)  /* 110592 */
#define NCHUNK 32               /* single emulation phase */

__global__ __launch_bounds__(256, 2)
void mma_gemm_kernel(const __half* __restrict__ Ahi,
                     const __half* __restrict__ B0,
                     const float* __restrict__ bias0,
                     const __half* __restrict__ B1,
                     const float* __restrict__ bias1,
                     float* __restrict__ C, int N, int mode)
{
    extern __shared__ char smem[];
    const uint32_t smem_base = smem_to_u32(smem);
    const int tid = threadIdx.x;
    const int wid = tid >> 5;
    const int lid = tid & 31;
    const int bm = blockIdx.y * BM;
    const bool isKV = (mode == 1) && (blockIdx.x >= 16);
    const int bn = isKV ? (blockIdx.x - 16) * BN : blockIdx.x * BN;
    const __half* Bh = isKV ? B1 : B0;
    const float* bias = isKV ? bias1 : bias0;

    auto issue = [&](int c, int stage) {
        const size_t k0 = (size_t)c * BKH;
        const uint32_t sA = smem_base + stage * STG_BYTES;
        const uint32_t sB = sA + STG_A;
#pragma unroll
        for (int j = 0; j < 4; j++) {
            int seg = tid + j * 256;
            int r = seg >> 3, s = seg & 7;
            CP_ASYNC16(sA + r * APITCH_B + s * 16,
                       (const char*)(Ahi + (size_t)(bm + r) * HID_C + k0 + s * 8));
        }
#pragma unroll
        for (int j = 0; j < 4; j++) {
            int seg = tid + j * 256;
            int r = seg >> 3, s = seg & 7;
            CP_ASYNC16(sB + r * APITCH_B + s * 16,
                       (const char*)(Bh + (size_t)(bn + r) * HID_C + k0 + s * 8));
        }
    };

    float acc[4][4][4];
#pragma unroll
    for (int i = 0; i < 4; i++)
#pragma unroll
        for (int j = 0; j < 4; j++)
#pragma unroll
            for (int q = 0; q < 4; q++) acc[i][j][q] = 0.f;

    issue(0, 0); CP_COMMIT();
    issue(1, 1); CP_COMMIT();

    const int wm = (wid >> 2) * 64;
    const int wn = (wid & 3) * 32;
    const int mat = lid >> 3;
    const int wi = lid & 7;

    for (int t = 0; t < NCHUNK; t++) {
        CP_WAIT1();
        __syncthreads();
        if (t + 2 < NCHUNK) issue(t + 2, (t + 2) % NSTAGE);
        CP_COMMIT();

        const uint32_t aBase = smem_base + (t % NSTAGE) * STG_BYTES;
        const uint32_t bBase = aBase + STG_A;
#pragma unroll
        for (int ks = 0; ks < 4; ks++) {
            const int k0 = ks * 16;
            uint32_t afr[4][4];
            uint32_t bfr[4][2];
#pragma unroll
            for (int i = 0; i < 4; i++) {
                int row = wm + i * 16 + (mat & 1) * 8 + wi;
                int col = k0 + (mat >> 1) * 8;
                LDMATRIX_X4(afr[i][0], afr[i][1], afr[i][2], afr[i][3],
                            aBase + row * APITCH_B + col * 2);
            }
#pragma unroll
            for (int jj = 0; jj < 2; jj++) {
                int n = wn + jj * 16 + (mat >> 1) * 8 + wi;
                int k = k0 + (mat & 1) * 8;
                LDMATRIX_X4(bfr[2 * jj][0], bfr[2 * jj][1],
                            bfr[2 * jj + 1][0], bfr[2 * jj + 1][1],
                            bBase + n * APITCH_B + k * 2);
            }
#pragma unroll
            for (int i = 0; i < 4; i++)
#pragma unroll
                for (int j = 0; j < 4; j++)
                    MMA_F16(acc[i][j], afr[i], bfr[j]);
        }
    }

    const int g = lid >> 2;
    const int tq = lid & 3;
#pragma unroll
    for (int i = 0; i < 4; i++) {
#pragma unroll
        for (int j = 0; j < 4; j++) {
            int row0 = bm + wm + i * 16 + g;
            int col = bn + wn + j * 8 + tq * 2;
            float b0 = bias[col], b1 = bias[col + 1];
            float v00 = acc[i][j][0] + b0, v01 = acc[i][j][1] + b1;
            float v10 = acc[i][j][2] + b0, v11 = acc[i][j][3] + b1;
            if (mode == 0) {
                *(float2*)(C + (size_t)row0 * N + col) = make_float2(v00, v01);
                *(float2*)(C + (size_t)(row0 + 8) * N + col) = make_float2(v10, v11);
            } else if (!isKV) {   // Q: fold softmax scale (log2 domain), fp16
                v00 *= SOFTMAX_SCALE_LOG2; v01 *= SOFTMAX_SCALE_LOG2;
                v10 *= SOFTMAX_SCALE_LOG2; v11 *= SOFTMAX_SCALE_LOG2;
                *(uint32_t*)&gQhi[(size_t)row0 * HID_C + col] = pack2h(v00, v01);
                *(uint32_t*)&gQhi[(size_t)(row0 + 8) * HID_C + col] = pack2h(v10, v11);
            } else {
                if (bn == 0) {    // K: hi only
                    *(uint32_t*)&gKhi[(size_t)row0 * HEAD_D + col] =
                        pack2h(v00, v01);
                    *(uint32_t*)&gKhi[(size_t)(row0 + 8) * HEAD_D + col] =
                        pack2h(v10, v11);
                } else {          // V: transpose, hi only
                    int d0 = col - 128;
                    float vs[2][2] = {{v00, v01}, {v10, v11}};
#pragma unroll
                    for (int rr = 0; rr < 2; rr++)
#pragma unroll
                        for (int cc = 0; cc < 2; cc++)
                            gVthi[(size_t)(d0 + cc) * M_ROWS + row0 + rr * 8] =
                                __float2half_rn(vs[rr][cc]);
                }
            }
        }
    }
}

// ---------------------------------------------------------------------------
// Flash attention, tensor-core fp16; Q/K/V/P all fp16 (single QK pass); causal.
// CTA: 128 q-rows x (head, batch); 8 warps (m16); KV tile FN=128.
// Smem: Q [128][128]h (32KB) + 2 stages {K [128][128]h, Vt [128][128]h}
// ---------------------------------------------------------------------------
#define FM 128
#define FN 128
#define SMQ_HI 0
#define SM_STG 32768
#define STGSZ 65536
#define SK_OFF 0
#define SV_OFF 32768
#define FA_SMEM (32768 + 2 * STGSZ)   /* 163840 */

__global__ __launch_bounds__(256, 1)
void flash_mma_kernel()
{
    extern __shared__ char sm[];
    const uint32_t sb = smem_to_u32(sm);
    const int tid = threadIdx.x;
    const int wid = tid >> 5;
    const int lid = tid & 31;
    const int qt = (int)gridDim.x - 1 - (int)blockIdx.x;  // heavy blocks first
    const int h = blockIdx.y;
    const int b = blockIdx.z;
    const int m0 = qt * FM;
    const int wm = wid * 16;
    const size_t bS = (size_t)b * S_LEN;
    const int g = lid >> 2, tq = lid & 3;
    const int ntiles = qt + 1;

    auto issueQ = [&]() {
#pragma unroll
        for (int j = 0; j < 8; j++) {
            int idx = tid + j * 256;
            int r = idx >> 4, c16 = idx & 15;
            const __half* src =
                gQhi + (bS + m0 + r) * HID_C + h * HEAD_D + c16 * 8;
            CP_ASYNC16(sb + SMQ_HI + r * 256 + ((c16 ^ (r & 7)) << 4),
                       (const char*)src);
        }
    };
    auto issueKV = [&](int t, int s) {
        const uint32_t st = sb + SM_STG + s * STGSZ;
        const int n0 = t * FN;
#pragma unroll
        for (int j = 0; j < 8; j++) {
            int idx = tid + j * 256;
            int r = idx >> 4, c16 = idx & 15;
            const __half* src = gKhi + (bS + n0 + r) * HEAD_D + c16 * 8;
            CP_ASYNC16(st + SK_OFF + r * 256 + ((c16 ^ (r & 7)) << 4),
                       (const char*)src);
        }
#pragma unroll
        for (int j = 0; j < 8; j++) {
            int idx = tid + j * 256;
            int r = idx >> 4, c16 = idx & 15;
            const __half* src = gVthi + (size_t)r * M_ROWS + bS + n0 + c16 * 8;
            CP_ASYNC16(st + SV_OFF + r * 256 + ((c16 ^ (r & 7)) << 4),
                       (const char*)src);
        }
    };

    issueQ();
    issueKV(0, 0);
    CP_COMMIT();
    if (ntiles > 1) issueKV(1, 1);
    CP_COMMIT();
    CP_WAIT1();
    __syncthreads();

    float oacc[16][4];
#pragma unroll
    for (int i = 0; i < 16; i++)
#pragma unroll
        for (int q = 0; q < 4; q++) oacc[i][q] = 0.f;
    float mst[2] = {-1e30f, -1e30f};
    float lst[2] = {0.f, 0.f};

    const int mat = lid >> 3;
    const int wi = lid & 7;

    for (int t = 0; t < ntiles; t++) {
        const uint32_t st = sb + SM_STG + (t & 1) * STGSZ;

        // ---- S = Q K^T : single pass (Q fp16) ----
        float sacc[16][4];
#pragma unroll
        for (int i = 0; i < 16; i++)
#pragma unroll
            for (int q = 0; q < 4; q++) sacc[i][q] = 0.f;

        {
            const uint32_t kb = st + SK_OFF;
#pragma unroll
            for (int kk = 0; kk < 8; kk++) {
                uint32_t ah[4];
                {
                    int r = wm + (lid & 15);
                    int c16 = 2 * kk + (lid >> 4);
                    uint32_t off = r * 256 + ((c16 ^ (r & 7)) << 4);
                    LDMATRIX_X4(ah[0], ah[1], ah[2], ah[3], sb + SMQ_HI + off);
                }
#pragma unroll
                for (int jj = 0; jj < 8; jj++) {
                    int r = jj * 16 + (mat >> 1) * 8 + wi;
                    int c16 = 2 * kk + (mat & 1);
                    uint32_t v[4];
                    LDMATRIX_X4(v[0], v[1], v[2], v[3],
                                kb + r * 256 + ((c16 ^ (r & 7)) << 4));
                    MMA_F16(sacc[2 * jj], ah, v);
                    MMA_F16(sacc[2 * jj + 1], ah, (v + 2));
                }
            }
        }

        // ---- causal mask (diagonal tile only) ----
        if (t == qt) {
#pragma unroll
            for (int nb = 0; nb < 16; nb++)
#pragma unroll
                for (int q = 0; q < 4; q++) {
                    int col = t * FN + nb * 8 + tq * 2 + (q & 1);
                    int row = m0 + wm + g + (q >> 1) * 8;
                    if (col > row) sacc[nb][q] = -1e30f;
                }
        }

        // ---- online softmax (log2 domain) ----
#pragma unroll
        for (int hf = 0; hf < 2; hf++) {
            float tm = -1e30f;
#pragma unroll
            for (int nb = 0; nb < 16; nb++) {
                tm = fmaxf(tm, fmaxf(sacc[nb][2 * hf], sacc[nb][2 * hf + 1]));
            }
            tm = fmaxf(tm, __shfl_xor_sync(0xffffffffu, tm, 1));
            tm = fmaxf(tm, __shfl_xor_sync(0xffffffffu, tm, 2));
            float mn = fmaxf(mst[hf], tm);
            float corr = exp2f(mst[hf] - mn);
            mst[hf] = mn;
            float sum = 0.f;
#pragma unroll
            for (int nb = 0; nb < 16; nb++) {
#pragma unroll
                for (int e = 0; e < 2; e++) {
                    float p = exp2f(sacc[nb][2 * hf + e] - mn);
                    sacc[nb][2 * hf + e] = p;
                    sum += p;
                }
            }
            sum += __shfl_xor_sync(0xffffffffu, sum, 1);
            sum += __shfl_xor_sync(0xffffffffu, sum, 2);
            lst[hf] = lst[hf] * corr + sum;
#pragma unroll
            for (int nb = 0; nb < 16; nb++) {
                oacc[nb][2 * hf + 0] *= corr;
                oacc[nb][2 * hf + 1] *= corr;
            }
        }

        // ---- O += Ph Vh (single-pass PV; P rounded to fp16) ----
#pragma unroll
        for (int kk = 0; kk < 8; kk++) {
            uint32_t ah[4];
            ah[0] = pack2h(sacc[2 * kk][0], sacc[2 * kk][1]);
            ah[1] = pack2h(sacc[2 * kk][2], sacc[2 * kk][3]);
            ah[2] = pack2h(sacc[2 * kk + 1][0], sacc[2 * kk + 1][1]);
            ah[3] = pack2h(sacc[2 * kk + 1][2], sacc[2 * kk + 1][3]);
#pragma unroll
            for (int jj = 0; jj < 8; jj++) {
                int r = jj * 16 + (mat >> 1) * 8 + wi;
                int c16 = 2 * kk + (mat & 1);
                uint32_t v[4];
                LDMATRIX_X4(v[0], v[1], v[2], v[3],
                            st + SV_OFF + r * 256 + ((c16 ^ (r & 7)) << 4));
                MMA_F16(oacc[2 * jj], ah, v);
                MMA_F16(oacc[2 * jj + 1], ah, (v + 2));
            }
        }

        __syncthreads();
        if (t + 2 < ntiles) issueKV(t + 2, t & 1);
        CP_COMMIT();
        if (t + 1 < ntiles) {
            CP_WAIT1();
        } else {
            CP_WAIT0();
        }
        __syncthreads();
    }

    // ---- epilogue: O/l -> fp16 into gA_hi ----
#pragma unroll
    for (int hf = 0; hf < 2; hf++) {
        float inv = 1.f / lst[hf];
        size_t row = bS + m0 + wm + g + hf * 8;
#pragma unroll
        for (int nb = 0; nb < 16; nb++) {
            float v0 = oacc[nb][2 * hf] * inv;
            float v1 = oacc[nb][2 * hf + 1] * inv;
            size_t off = row * HID_C + h * HEAD_D + nb * 8 + tq * 2;
            *(uint32_t*)&gA_hi[off] = pack2h(v0, v1);
        }
    }
}

// ---------------------------------------------------------------------------
extern "C" void kernel_launch(void* const* d_in, const int* in_sizes, int n_in,
                              void* d_out, int out_size)
{
    (void)in_sizes; (void)n_in; (void)out_size;
    const float* hs  = (const float*)d_in[0];
    /* d_in[1] = attention_mask (exact causal tril) applied analytically */
    const float* Wq  = (const float*)d_in[2];
    const float* bq  = (const float*)d_in[3];
    const float* Wkv = (const float*)d_in[4];
    const float* bkv = (const float*)d_in[5];
    const float* Wp  = (const float*)d_in[6];
    const float* bp  = (const float*)d_in[7];
    float* out = (float*)d_out;

    __half *pAhi, *pWqh, *pWkh, *pWph;
    cudaGetSymbolAddress((void**)&pAhi, gA_hi);
    cudaGetSymbolAddress((void**)&pWqh, gWq_hi);
    cudaGetSymbolAddress((void**)&pWkh, gWkv_hi);
    cudaGetSymbolAddress((void**)&pWph, gWp_hi);

    cudaFuncSetAttribute(mma_gemm_kernel,
                         cudaFuncAttributeMaxDynamicSharedMemorySize, GEMM_SMEM);
    cudaFuncSetAttribute(flash_mma_kernel,
                         cudaFuncAttributeMaxDynamicSharedMemorySize, FA_SMEM);

    // 1. convert hidden states to fp16
    {
        int n4 = M_ROWS * HID_C / 4;
        conv_f32_kernel<<<(n4 + 255) / 256, 256>>>(hs, pAhi, n4);
    }
    // 2. fused transpose+convert of all three weights
    tconv_all_kernel<<<dim3(HID_C / 32, HID_C / 32, 3), dim3(32, 8)>>>(Wq, Wp, Wkv);

    // 3. fused Q + KV projection (single-product)
    mma_gemm_kernel<<<dim3(18, M_ROWS / BM), 256, GEMM_SMEM>>>(
        pAhi, pWqh, bq, pWkh, bkv, nullptr, HID_C, 1);
    // 4. attention -> gA_hi (fp16)
    flash_mma_kernel<<<dim3(S_LEN / FM, N_HEADS, B_SZ), 256, FA_SMEM>>>();
    // 5. out = attn @ Wp + bp (single-product)
    mma_gemm_kernel<<<dim3(16, M_ROWS / BM), 256, GEMM_SMEM>>>(
        pAhi, pWph, bp, nullptr, nullptr, out, HID_C, 0);
}